// round 12
// baseline (speedup 1.0000x reference)
#include <cuda_runtime.h>
#include <cuda_fp16.h>
#include <math.h>
#include <stdint.h>

// ---------------------------------------------------------------------------
// Problem constants: B=16, S=2048, D=64, NQ=6
// ---------------------------------------------------------------------------
#define NTOK   32768
#define SEQ    2048
#define NBATCH 16

typedef unsigned long long u64;

// ---------------------------------------------------------------------------
// Device scratch (static — no allocation)
// ---------------------------------------------------------------------------
static __device__ float  g_M[3 * 64 * 128];
static __device__ float  g_WZ[2 * 4 * 64];
static __device__ float  g_c2;
static __device__ float4 g_q[NTOK];
static __device__ float4 g_k[NTOK];    // pre-scaled: -2*c2*k
static __device__ float  g_qq[NTOK];
static __device__ float  g_kk[NTOK];   // pre-scaled: c2*kk
static __device__ __half g_vt[NBATCH * 64 * SEQ];   // [b][dim][s]  fp16 V^T

// ---------------------------------------------------------------------------
// Gate composition helpers
// ---------------------------------------------------------------------------
struct C2x2 { float re[4]; float im[4]; };

__device__ __forceinline__ C2x2 cmul(const C2x2& A, const C2x2& B) {
    C2x2 C;
    #pragma unroll
    for (int r = 0; r < 2; r++)
        #pragma unroll
        for (int c = 0; c < 2; c++) {
            float rr = 0.f, ii = 0.f;
            #pragma unroll
            for (int k = 0; k < 2; k++) {
                float ar = A.re[r*2+k], ai = A.im[r*2+k];
                float br = B.re[k*2+c], bi = B.im[k*2+c];
                rr += ar*br - ai*bi;
                ii += ar*bi + ai*br;
            }
            C.re[r*2+c] = rr; C.im[r*2+c] = ii;
        }
    return C;
}
__device__ __forceinline__ C2x2 mk_rx(float t) {
    float c = cosf(0.5f*t), s = sinf(0.5f*t);
    C2x2 M;
    M.re[0]=c;  M.im[0]=0.f;  M.re[1]=0.f; M.im[1]=-s;
    M.re[2]=0.f;M.im[2]=-s;   M.re[3]=c;   M.im[3]=0.f;
    return M;
}
__device__ __forceinline__ C2x2 mk_ry(float t) {
    float c = cosf(0.5f*t), s = sinf(0.5f*t);
    C2x2 M;
    M.re[0]=c;  M.im[0]=0.f;  M.re[1]=-s;  M.im[1]=0.f;
    M.re[2]=s;  M.im[2]=0.f;  M.re[3]=c;   M.im[3]=0.f;
    return M;
}
__device__ __forceinline__ C2x2 mk_u3(float t, float p, float l) {
    float c = cosf(0.5f*t), s = sinf(0.5f*t);
    C2x2 M;
    M.re[0]=c;              M.im[0]=0.f;
    M.re[1]=-cosf(l)*s;     M.im[1]=-sinf(l)*s;
    M.re[2]= cosf(p)*s;     M.im[2]= sinf(p)*s;
    M.re[3]= cosf(p+l)*c;   M.im[3]= sinf(p+l)*c;
    return M;
}

// ---------------------------------------------------------------------------
// Warp-level circuit sim primitives (validated R1)
// ---------------------------------------------------------------------------
__device__ __forceinline__ void apply_gate(const float* __restrict__ gp, int q, int lane,
                                           float& ar0, float& ai0, float& ar1, float& ai1) {
    float4 gA = *(const float4*)gp;
    float4 gB = *(const float4*)(gp + 4);
    if (q == 5) {
        float n0r = gA.x*ar0 - gA.y*ai0 + gA.z*ar1 - gA.w*ai1;
        float n0i = gA.x*ai0 + gA.y*ar0 + gA.z*ai1 + gA.w*ar1;
        float n1r = gB.x*ar0 - gB.y*ai0 + gB.z*ar1 - gB.w*ai1;
        float n1i = gB.x*ai0 + gB.y*ar0 + gB.z*ai1 + gB.w*ar1;
        ar0=n0r; ai0=n0i; ar1=n1r; ai1=n1i;
    } else {
        int sh = 4 - q;
        int lx = 1 << sh;
        int bit = (lane >> sh) & 1;
        float br0 = __shfl_xor_sync(0xffffffffu, ar0, lx);
        float bi0 = __shfl_xor_sync(0xffffffffu, ai0, lx);
        float br1 = __shfl_xor_sync(0xffffffffu, ar1, lx);
        float bi1 = __shfl_xor_sync(0xffffffffu, ai1, lx);
        float csr = bit ? gB.z : gA.x;
        float csi = bit ? gB.w : gA.y;
        float cor = bit ? gB.x : gA.z;
        float coi = bit ? gB.y : gA.w;
        float n0r = csr*ar0 - csi*ai0 + cor*br0 - coi*bi0;
        float n0i = csr*ai0 + csi*ar0 + cor*bi0 + coi*br0;
        float n1r = csr*ar1 - csi*ai1 + cor*br1 - coi*bi1;
        float n1i = csr*ai1 + csi*ar1 + cor*bi1 + coi*br1;
        ar0=n0r; ai0=n0i; ar1=n1r; ai1=n1i;
    }
}

__device__ __forceinline__ void apply_section(const float* __restrict__ sg, int base, int lane,
                                              float& ar0, float& ai0, float& ar1, float& ai1) {
    #pragma unroll
    for (int i = 0; i < 6; i++)
        apply_gate(sg + (base + i) * 8, i, lane, ar0, ai0, ar1, ai1);
}

__device__ __forceinline__ void apply_chain(int lane,
                                            float& ar0, float& ai0, float& ar1, float& ai1) {
    #pragma unroll
    for (int i = 0; i < 4; i++) {
        int lx = 1 << (3 - i);
        int cb = (lane >> (4 - i)) & 1;
        float br0 = __shfl_xor_sync(0xffffffffu, ar0, lx);
        float bi0 = __shfl_xor_sync(0xffffffffu, ai0, lx);
        float br1 = __shfl_xor_sync(0xffffffffu, ar1, lx);
        float bi1 = __shfl_xor_sync(0xffffffffu, ai1, lx);
        if (cb) { ar0=br0; ai0=bi0; ar1=br1; ai1=bi1; }
    }
    {
        int cb = lane & 1;
        float tr = ar0, ti = ai0;
        ar0 = cb ? ar1 : ar0;  ai0 = cb ? ai1 : ai0;
        ar1 = cb ? tr  : ar1;  ai1 = cb ? ti  : ai1;
    }
}

__device__ __forceinline__ float wredsum(float v) {
    #pragma unroll
    for (int o = 16; o > 0; o >>= 1) v += __shfl_xor_sync(0xffffffffu, v, o);
    return v;
}

// ---------------------------------------------------------------------------
// Precompute: grid=64 blocks x 32 threads — one warp per basis column.
// ---------------------------------------------------------------------------
__global__ void precompute_kernel(const float* __restrict__ enc_w,
                                  const float* __restrict__ q_w,
                                  const float* __restrict__ k_w,
                                  const float* __restrict__ v_w,
                                  const float* __restrict__ mq,
                                  const float* __restrict__ mk,
                                  const float* __restrict__ mv,
                                  const float* __restrict__ qW,
                                  const float* __restrict__ kW,
                                  const float* __restrict__ raw_tau) {
    __shared__ __align__(16) float sg[576];
    int tid = threadIdx.x;   // 0..31
    int lane = tid;

    // compose the 72 gates (each thread handles up to 3)
    for (int g = tid; g < 72; g += 32) {
        const float* w; const float* mw = nullptr;
        int sec, i; bool is_enc;
        if (g < 18) { w = enc_w; sec = g/6; i = g%6; is_enc = true; }
        else {
            int gg = g - 18; int xq = gg/18; sec = (gg%18)/6; i = gg%6; is_enc = false;
            w  = (xq==0) ? q_w : (xq==1) ? k_w : v_w;
            mw = (xq==0) ? mq  : (xq==1) ? mk  : mv;
        }
        C2x2 G;
        if (sec == 0)      G = cmul(mk_ry(w[i*3+1]), mk_rx(w[i*3+0]));
        else if (sec == 1) G = cmul(cmul(mk_ry(w[18+i*3+1]), mk_rx(w[18+i*3+0])),
                                    mk_ry(w[i*3+2]));
        else {
            if (is_enc) G = mk_ry(w[18+i*3+2]);
            else        G = cmul(mk_u3(mw[i*3+0], mw[i*3+1], mw[i*3+2]),
                                 mk_ry(w[18+i*3+2]));
        }
        float* o = &sg[g*8];
        o[0]=G.re[0]; o[1]=G.im[0]; o[2]=G.re[1]; o[3]=G.im[1];
        o[4]=G.re[2]; o[5]=G.im[2]; o[6]=G.re[3]; o[7]=G.im[3];
    }

    if (blockIdx.x == 0) {
        if (tid == 0) {
            float tau = log1pf(expf(raw_tau[0])) + 1e-9f;
            g_c2 = -1.4426950408889634f / tau;
        }
        for (int e = tid; e < 512; e += 32) {
            int br = e >> 8, j = (e >> 6) & 3, a = e & 63;
            const float* w = br ? kW : qW;
            float acc = 0.f;
            #pragma unroll
            for (int i = 0; i < 6; i++) {
                float sgn = ((a >> (5 - i)) & 1) ? -1.f : 1.f;
                acc += w[j*6 + i] * sgn;
            }
            g_WZ[e] = acc;
        }
    }
    __syncthreads();

    int c = blockIdx.x;      // basis column 0..63

    float ar0 = (2*lane     == c) ? 1.f : 0.f;
    float ar1 = (2*lane + 1 == c) ? 1.f : 0.f;
    float ai0 = 0.f, ai1 = 0.f;

    apply_section(sg, 0,  lane, ar0, ai0, ar1, ai1);
    apply_chain(lane, ar0, ai0, ar1, ai1);
    apply_section(sg, 6,  lane, ar0, ai0, ar1, ai1);
    apply_chain(lane, ar0, ai0, ar1, ai1);
    apply_section(sg, 12, lane, ar0, ai0, ar1, ai1);

    float cr0 = ar0, ci0 = ai0, cr1 = ar1, ci1 = ai1;

    #pragma unroll
    for (int br = 0; br < 3; br++) {
        ar0 = cr0; ai0 = ci0; ar1 = cr1; ai1 = ci1;
        int gb = 18 + br * 18;
        apply_section(sg, gb,      lane, ar0, ai0, ar1, ai1);
        apply_chain(lane, ar0, ai0, ar1, ai1);
        apply_section(sg, gb + 6,  lane, ar0, ai0, ar1, ai1);
        apply_chain(lane, ar0, ai0, ar1, ai1);
        apply_section(sg, gb + 12, lane, ar0, ai0, ar1, ai1);

        float* base = &g_M[(br * 64 + c) * 128];
        *(float2*)&base[2*lane]      = make_float2(ar0, ar1);
        *(float2*)&base[64 + 2*lane] = make_float2(ai0, ai1);
    }
}

// ---------------------------------------------------------------------------
// f32x2 helpers (phase1)
// ---------------------------------------------------------------------------
__device__ __forceinline__ u64 pk2(float x) {
    u64 r; asm("mov.b64 %0, {%1, %1};" : "=l"(r) : "f"(x)); return r;
}
__device__ __forceinline__ void fma2(u64& d, u64 a, u64 b) {
    asm("fma.rn.f32x2 %0, %1, %2, %0;" : "+l"(d) : "l"(a), "l"(b));
}
__device__ __forceinline__ float ex2f(float x) {
    float y; asm("ex2.approx.ftz.f32 %0, %1;" : "=f"(y) : "f"(x)); return y;
}

// ---------------------------------------------------------------------------
// Phase 1 (unchanged — validated)
// ---------------------------------------------------------------------------
#define SX_STRIDE 68
#define VT_STRIDE 66
#define P1_SMEM_FLOATS (64*SX_STRIDE + 8320 + 64 + 512 + 16 + (64*VT_STRIDE)/2)

__global__ __launch_bounds__(256) void phase1_kernel(
    const float* __restrict__ x, const float* __restrict__ inp_scale,
    const float* __restrict__ qB, const float* __restrict__ kB,
    const float* __restrict__ lng, const float* __restrict__ lnb) {

    extern __shared__ __align__(16) float sm[];
    float* sX   = sm;
    float* sM   = sX + 64*SX_STRIDE;
    float* sC   = sM;
    float* sInv = sM + 8320;
    float* sWZ  = sInv + 64;
    float* sLN  = sWZ + 512;
    __half* sVT = (__half*)(sLN + 16);

    int tid = threadIdx.x;
    int lane = tid & 31, warp = tid >> 5;
    int tok0 = blockIdx.x * 64;

    {
        int t = tid & 63, cg = tid >> 6;
        const float4* xg = (const float4*)(x + (size_t)(tok0 + t) * 64 + cg * 16);
        #pragma unroll
        for (int i = 0; i < 4; i++) {
            float4 v = xg[i];
            int c = cg * 16 + i * 4;
            float4 sv = *(const float4*)(inp_scale + c);
            sX[(c+0)*SX_STRIDE + t] = v.x * sv.x;
            sX[(c+1)*SX_STRIDE + t] = v.y * sv.y;
            sX[(c+2)*SX_STRIDE + t] = v.z * sv.z;
            sX[(c+3)*SX_STRIDE + t] = v.w * sv.w;
        }
    }
    if (tid < 16)  sLN[tid] = (tid < 4) ? qB[tid] : (tid < 8) ? kB[tid-4]
                             : (tid < 12) ? lng[tid-8] : lnb[tid-12];
    for (int e = tid; e < 512; e += 256) sWZ[e] = g_WZ[e];
    __syncthreads();

    #pragma unroll
    for (int it = 0; it < 8; it++) {
        int t = it * 8 + warp;
        float a0 = sX[lane*SX_STRIDE + t];
        float a1 = sX[(lane+32)*SX_STRIDE + t];
        float s = wredsum(a0*a0 + a1*a1);
        if (lane == 0) {
            float nr = sqrtf(s) + 1e-9f;
            sInv[t] = 1.f / (nr * nr);
        }
    }

    int rg = tid & 15, tg = tid >> 4;
    int r0 = rg * 8, t0 = tg * 4;

    for (int br = 0; br < 3; br++) {
        __syncthreads();
        {
            const float4* mg = (const float4*)&g_M[br * 64 * 128];
            float4* ms = (float4*)sM;
            #pragma unroll
            for (int i = 0; i < 8; i++) ms[i * 256 + tid] = mg[i * 256 + tid];
        }
        __syncthreads();

        u64 acc[4][4] = {};
        #pragma unroll 4
        for (int k = 0; k < 64; k++) {
            ulonglong2 mA = *(const ulonglong2*)&sM[k*128 + r0];
            ulonglong2 mB = *(const ulonglong2*)&sM[k*128 + r0 + 4];
            float4 xv = *(const float4*)&sX[k*SX_STRIDE + t0];
            u64 x0 = pk2(xv.x), x1 = pk2(xv.y), x2 = pk2(xv.z), x3 = pk2(xv.w);
            fma2(acc[0][0], mA.x, x0); fma2(acc[0][1], mA.x, x1);
            fma2(acc[0][2], mA.x, x2); fma2(acc[0][3], mA.x, x3);
            fma2(acc[1][0], mA.y, x0); fma2(acc[1][1], mA.y, x1);
            fma2(acc[1][2], mA.y, x2); fma2(acc[1][3], mA.y, x3);
            fma2(acc[2][0], mB.x, x0); fma2(acc[2][1], mB.x, x1);
            fma2(acc[2][2], mB.x, x2); fma2(acc[2][3], mB.x, x3);
            fma2(acc[3][0], mB.y, x0); fma2(acc[3][1], mB.y, x1);
            fma2(acc[3][2], mB.y, x2); fma2(acc[3][3], mB.y, x3);
        }
        __syncthreads();
        #pragma unroll
        for (int j = 0; j < 4; j++)
            #pragma unroll
            for (int i = 0; i < 4; i++)
                *(u64*)&sC[(t0+j)*130 + r0 + 2*i] = acc[i][j];
        __syncthreads();

        if (br < 2) {
            float2 wz0 = *(float2*)&sWZ[br*256 +   0 + 2*lane];
            float2 wz1 = *(float2*)&sWZ[br*256 +  64 + 2*lane];
            float2 wz2 = *(float2*)&sWZ[br*256 + 128 + 2*lane];
            float2 wz3 = *(float2*)&sWZ[br*256 + 192 + 2*lane];
            #pragma unroll
            for (int it = 0; it < 8; it++) {
                int t = it * 8 + warp;
                float inv = sInv[t];
                float2 re = *(float2*)&sC[t*130 + 2*lane];
                float2 im = *(float2*)&sC[t*130 + 64 + 2*lane];
                float p0 = (re.x*re.x + im.x*im.x) * inv;
                float p1 = (re.y*re.y + im.y*im.y) * inv;
                float o0 = wredsum(p0*wz0.x + p1*wz0.y);
                float o1 = wredsum(p0*wz1.x + p1*wz1.y);
                float o2 = wredsum(p0*wz2.x + p1*wz2.y);
                float o3 = wredsum(p0*wz3.x + p1*wz3.y);
                if (lane == 0) {
                    float o[4];
                    o[0] = o0 + sLN[br*4+0]; o[1] = o1 + sLN[br*4+1];
                    o[2] = o2 + sLN[br*4+2]; o[3] = o3 + sLN[br*4+3];
                    float m = 0.25f * (o[0]+o[1]+o[2]+o[3]);
                    float var = 0.f;
                    #pragma unroll
                    for (int j = 0; j < 4; j++) { float d = o[j]-m; var += d*d; }
                    var *= 0.25f;
                    float rstd = rsqrtf(var + 1e-5f);
                    float r[4], qq = 0.f;
                    #pragma unroll
                    for (int j = 0; j < 4; j++) {
                        r[j] = (o[j]-m)*rstd*sLN[8+j] + sLN[12+j];
                        qq += r[j]*r[j];
                    }
                    int token = tok0 + t;
                    if (br == 0) {
                        g_q[token] = make_float4(r[0], r[1], r[2], r[3]);
                        g_qq[token] = qq;
                    } else {
                        float c2l = g_c2;
                        float s2 = -2.f * c2l;
                        g_k[token] = make_float4(r[0]*s2, r[1]*s2, r[2]*s2, r[3]*s2);
                        g_kk[token] = c2l * qq;
                    }
                }
            }
        } else {
            #pragma unroll
            for (int it = 0; it < 8; it++) {
                int t = it * 8 + warp;
                float inv = sInv[t];
                float2 re = *(float2*)&sC[t*130 + 2*lane];
                float2 im = *(float2*)&sC[t*130 + 64 + 2*lane];
                float p0 = (re.x*re.x + im.x*im.x) * inv;
                float p1 = (re.y*re.y + im.y*im.y) * inv;
                float s1 = wredsum(p0 + p1);
                float s2 = wredsum(p0*p0 + p1*p1);
                float m   = s1 * (1.f/64.f);
                float var = s2 * (1.f/64.f) - m*m;
                float rstd = rsqrtf(var + 1e-5f);
                sVT[(2*lane)   * VT_STRIDE + t] = __float2half((p0 - m) * rstd);
                sVT[(2*lane+1) * VT_STRIDE + t] = __float2half((p1 - m) * rstd);
            }
        }
    }

    __syncthreads();
    {
        int bb = tok0 >> 11, s0 = tok0 & 2047;
        #pragma unroll
        for (int e = tid; e < 2048; e += 256) {
            int dim = e >> 5, i = e & 31;
            __half2 val = *(__half2*)&sVT[dim * VT_STRIDE + 2*i];
            *(__half2*)&g_vt[((size_t)bb * 64 + dim) * SEQ + s0 + 2*i] = val;
        }
    }
}

// ---------------------------------------------------------------------------
// Phase 2: FA2, alpha pipelined, 4 V buffers, unrolled by 2 chunks
// (explicit Af/Afn alternation — no register rotate), barrier per group.
// ---------------------------------------------------------------------------
__device__ __forceinline__ uint32_t smem_to_u32(const void* p) {
    uint32_t a;
    asm("{ .reg .u64 t; cvta.to.shared.u64 t, %1; cvt.u32.u64 %0, t; }"
        : "=r"(a) : "l"(p));
    return a;
}

#define LDSM_X4(r, a) \
    asm volatile("ldmatrix.sync.aligned.m8n8.x4.shared.b16 {%0,%1,%2,%3}, [%4];" \
                 : "=r"((r)[0]), "=r"((r)[1]), "=r"((r)[2]), "=r"((r)[3]) : "r"(a))

__device__ __forceinline__ void mma_f16(float* d, const uint32_t* a, const uint32_t* b) {
    asm volatile(
        "mma.sync.aligned.m16n8k16.row.col.f32.f16.f16.f32 "
        "{%0,%1,%2,%3}, {%4,%5,%6,%7}, {%8,%9}, {%0,%1,%2,%3};"
        : "+f"(d[0]), "+f"(d[1]), "+f"(d[2]), "+f"(d[3])
        : "r"(a[0]), "r"(a[1]), "r"(a[2]), "r"(a[3]), "r"(b[0]), "r"(b[1]));
}

__device__ __forceinline__ void alpha_chunk(
    int kb, int l3, const float4& q0, const float4& q1,
    float qs0, float qs1, uint32_t Af[4][4], float& d0, float& d1) {
    #pragma unroll
    for (int kf = 0; kf < 4; kf++) {
        int kidx = kb + kf * 16 + l3 * 2;
        #pragma unroll
        for (int cc = 0; cc < 2; cc++) {
            int ki = kidx + cc * 8;
            float4 ka = g_k[ki];
            float4 kb4 = g_k[ki + 1];
            float2 kk2 = *(const float2*)&g_kk[ki];
            float e00 = qs0 + kk2.x + ka.x*q0.x + ka.y*q0.y + ka.z*q0.z + ka.w*q0.w;
            float e01 = qs0 + kk2.y + kb4.x*q0.x + kb4.y*q0.y + kb4.z*q0.z + kb4.w*q0.w;
            float e10 = qs1 + kk2.x + ka.x*q1.x + ka.y*q1.y + ka.z*q1.z + ka.w*q1.w;
            float e11 = qs1 + kk2.y + kb4.x*q1.x + kb4.y*q1.y + kb4.z*q1.z + kb4.w*q1.w;
            float a00 = ex2f(fminf(e00, 0.f));
            float a01 = ex2f(fminf(e01, 0.f));
            float a10 = ex2f(fminf(e10, 0.f));
            float a11 = ex2f(fminf(e11, 0.f));
            d0 += a00 + a01;
            d1 += a10 + a11;
            __half2 h0 = __floats2half2_rn(a00, a01);
            __half2 h1 = __floats2half2_rn(a10, a11);
            Af[kf][cc*2 + 0] = *(uint32_t*)&h0;
            Af[kf][cc*2 + 1] = *(uint32_t*)&h1;
        }
    }
}

// MMA block for one chunk: 8 nt tiles x 4 kf
__device__ __forceinline__ void mma_block(
    uint32_t sbase, uint32_t bufR, int b_rloc, int b_cbo,
    const uint32_t Af[4][4], float acc[8][4]) {
    #pragma unroll
    for (int nt = 0; nt < 8; nt++) {
        uint32_t Bh[8];
        int brow = nt * 8 + b_rloc;
        #pragma unroll
        for (int ks2 = 0; ks2 < 2; ks2++) {
            int cb = ks2 * 4 + b_cbo;
            uint32_t addr = sbase + bufR + brow * 128 + ((cb ^ (brow & 7)) * 16);
            LDSM_X4(&Bh[ks2*4], addr);
        }
        #pragma unroll
        for (int kf = 0; kf < 4; kf++)
            mma_f16(acc[nt], Af[kf], &Bh[kf*2]);
    }
}

#define OFF_QV   0        // 2048
#define OFF_QQ   2048     // 512
#define OFF_B0   4096     // 4 buffers x 8192
#define P2_SMEM  36864

__global__ __launch_bounds__(256, 2) void phase2_mma_kernel(float* __restrict__ out) {
    extern __shared__ __align__(1024) char smem[];
    uint32_t sbase = smem_to_u32(smem);
    int tid = threadIdx.x, lane = tid & 31, w = tid >> 5;
    int b = blockIdx.y;
    int qbase = b * SEQ + blockIdx.x * 128;

    float4* qv = (float4*)(smem + OFF_QV);
    float*  qq = (float*)(smem + OFF_QQ);

    if (tid < 128) { qv[tid] = g_q[qbase + tid]; qq[tid] = g_qq[qbase + tid]; }

    const __half* vt_base = g_vt + (size_t)b * 64 * SEQ;

    int vd0 = tid >> 3,         vo0 = tid & 7;
    int vd1 = (tid + 256) >> 3, vo1 = tid & 7;
    uint32_t voff0 = vd0 * 128 + ((vo0 ^ (vd0 & 7)) * 16);
    uint32_t voff1 = vd1 * 128 + ((vo1 ^ (vd1 & 7)) * 16);

    // prologue: fill buf0 (chunk 0) and buf1 (chunk 1); prefetch chunks 2,3
    {
        uint4 a0 = *(const uint4*)(vt_base + (size_t)vd0 * SEQ + vo0 * 8);
        uint4 a1 = *(const uint4*)(vt_base + (size_t)vd1 * SEQ + vo1 * 8);
        uint4 b0 = *(const uint4*)(vt_base + (size_t)vd0 * SEQ + 64 + vo0 * 8);
        uint4 b1 = *(const uint4*)(vt_base + (size_t)vd1 * SEQ + 64 + vo1 * 8);
        *(uint4*)(smem + OFF_B0 + voff0) = a0;
        *(uint4*)(smem + OFF_B0 + voff1) = a1;
        *(uint4*)(smem + OFF_B0 + 8192 + voff0) = b0;
        *(uint4*)(smem + OFF_B0 + 8192 + voff1) = b1;
    }
    uint4 pva0 = *(const uint4*)(vt_base + (size_t)vd0 * SEQ + 128 + vo0 * 8);
    uint4 pva1 = *(const uint4*)(vt_base + (size_t)vd1 * SEQ + 128 + vo1 * 8);
    uint4 pvb0 = *(const uint4*)(vt_base + (size_t)vd0 * SEQ + 192 + vo0 * 8);
    uint4 pvb1 = *(const uint4*)(vt_base + (size_t)vd1 * SEQ + 192 + vo1 * 8);
    __syncthreads();

    int l3 = lane & 3, rloc = lane >> 2;
    int r0 = w * 16 + rloc, r1 = r0 + 8;
    float4 q0 = qv[r0], q1 = qv[r1];
    float c2 = g_c2;
    float qs0 = c2 * qq[r0], qs1 = c2 * qq[r1];

    float d0 = 0.f, d1 = 0.f;
    float acc[8][4] = {};

    int b_rloc = lane & 7;
    int b_cbo  = lane >> 3;

    uint32_t Af[4][4], Afn[4][4];
    alpha_chunk(b * SEQ, l3, q0, q1, qs0, qs1, Af, d0, d1);

    #pragma unroll 1
    for (int kc = 0; kc < 32; kc += 2) {
        // stage chunks kc+2, kc+3 (already prefetched), prefetch kc+4, kc+5
        if (kc < 30) {
            uint32_t bufW = OFF_B0 + ((kc + 2) & 3) * 8192;
            *(uint4*)(smem + bufW + voff0) = pva0;
            *(uint4*)(smem + bufW + voff1) = pva1;
            uint32_t bufW2 = OFF_B0 + ((kc + 3) & 3) * 8192;
            *(uint4*)(smem + bufW2 + voff0) = pvb0;
            *(uint4*)(smem + bufW2 + voff1) = pvb1;
            if (kc < 28) {
                int kn = (kc + 4) * 64;
                pva0 = *(const uint4*)(vt_base + (size_t)vd0 * SEQ + kn + vo0 * 8);
                pva1 = *(const uint4*)(vt_base + (size_t)vd1 * SEQ + kn + vo1 * 8);
                int kn2 = (kc + 5) * 64;
                if (kc < 27) {
                    pvb0 = *(const uint4*)(vt_base + (size_t)vd0 * SEQ + kn2 + vo0 * 8);
                    pvb1 = *(const uint4*)(vt_base + (size_t)vd1 * SEQ + kn2 + vo1 * 8);
                }
            }
        }

        // chunk kc: alpha(kc+1) -> Afn  ||  MMA(kc) with Af
        alpha_chunk(b * SEQ + (kc + 1) * 64, l3, q0, q1, qs0, qs1, Afn, d0, d1);
        mma_block(sbase, OFF_B0 + (kc & 3) * 8192, b_rloc, b_cbo, Af, acc);

        // chunk kc+1: alpha(kc+2) -> Af  ||  MMA(kc+1) with Afn
        if (kc < 30)
            alpha_chunk(b * SEQ + (kc + 2) * 64, l3, q0, q1, qs0, qs1, Af, d0, d1);
        mma_block(sbase, OFF_B0 + ((kc + 1) & 3) * 8192, b_rloc, b_cbo, Afn, acc);

        __syncthreads();
    }

    d0 += __shfl_xor_sync(0xffffffffu, d0, 1);
    d0 += __shfl_xor_sync(0xffffffffu, d0, 2);
    d1 += __shfl_xor_sync(0xffffffffu, d1, 1);
    d1 += __shfl_xor_sync(0xffffffffu, d1, 2);
    float rdT = 1.f / (d0 + 1e-9f);
    float rdB = 1.f / (d1 + 1e-9f);

    int cl = l3 * 2;
    #pragma unroll
    for (int nt = 0; nt < 8; nt++) {
        *(float2*)&out[(size_t)(qbase + r0) * 64 + nt*8 + cl] =
            make_float2(acc[nt][0] * rdT, acc[nt][1] * rdT);
        *(float2*)&out[(size_t)(qbase + r1) * 64 + nt*8 + cl] =
            make_float2(acc[nt][2] * rdB, acc[nt][3] * rdB);
    }
}

// ---------------------------------------------------------------------------
// Launch
// ---------------------------------------------------------------------------
extern "C" void kernel_launch(void* const* d_in, const int* in_sizes, int n_in,
                              void* d_out, int out_size) {
    const float* x         = (const float*)d_in[0];
    const float* inp_scale = (const float*)d_in[1];
    const float* enc_w     = (const float*)d_in[2];
    const float* q_w       = (const float*)d_in[3];
    const float* k_w       = (const float*)d_in[4];
    const float* v_w       = (const float*)d_in[5];
    const float* mq        = (const float*)d_in[6];
    const float* mk        = (const float*)d_in[7];
    const float* mv        = (const float*)d_in[8];
    const float* qW        = (const float*)d_in[9];
    const float* qB        = (const float*)d_in[10];
    const float* kW        = (const float*)d_in[11];
    const float* kB        = (const float*)d_in[12];
    const float* lng       = (const float*)d_in[13];
    const float* lnb       = (const float*)d_in[14];
    const float* raw_tau   = (const float*)d_in[15];

    static int attr_set = 0;
    const int P1_SMEM = P1_SMEM_FLOATS * 4;
    if (!attr_set) {
        cudaFuncSetAttribute(phase1_kernel,
                             cudaFuncAttributeMaxDynamicSharedMemorySize, P1_SMEM);
        cudaFuncSetAttribute(phase2_mma_kernel,
                             cudaFuncAttributeMaxDynamicSharedMemorySize, P2_SMEM);
        attr_set = 1;
    }

    precompute_kernel<<<64, 32>>>(enc_w, q_w, k_w, v_w, mq, mk, mv, qW, kW, raw_tau);
    phase1_kernel<<<NTOK / 64, 256, P1_SMEM>>>(x, inp_scale, qB, kB, lng, lnb);
    phase2_mma_kernel<<<dim3(SEQ / 128, NBATCH), 256, P2_SMEM>>>((float*)d_out);
}

// round 13
// speedup vs baseline: 1.1916x; 1.1916x over previous
#include <cuda_runtime.h>
#include <cuda_fp16.h>
#include <math.h>
#include <stdint.h>

// ---------------------------------------------------------------------------
// Problem constants: B=16, S=2048, D=64, NQ=6
// ---------------------------------------------------------------------------
#define NTOK   32768
#define SEQ    2048
#define NBATCH 16

typedef unsigned long long u64;

// ---------------------------------------------------------------------------
// Device scratch (static — no allocation)
// ---------------------------------------------------------------------------
static __device__ float  g_M[3 * 64 * 128];
static __device__ float  g_WZ[2 * 4 * 64];
static __device__ float  g_c2;
static __device__ float4 g_q[NTOK];
static __device__ float4 g_k[NTOK];    // pre-scaled: -2*c2*k
static __device__ float  g_qq[NTOK];
static __device__ float  g_kk[NTOK];   // pre-scaled: c2*kk
static __device__ __half g_vt[NBATCH * 64 * SEQ];   // [b][dim][s]  fp16 V^T

// ---------------------------------------------------------------------------
// Gate composition helpers
// ---------------------------------------------------------------------------
struct C2x2 { float re[4]; float im[4]; };

__device__ __forceinline__ C2x2 cmul(const C2x2& A, const C2x2& B) {
    C2x2 C;
    #pragma unroll
    for (int r = 0; r < 2; r++)
        #pragma unroll
        for (int c = 0; c < 2; c++) {
            float rr = 0.f, ii = 0.f;
            #pragma unroll
            for (int k = 0; k < 2; k++) {
                float ar = A.re[r*2+k], ai = A.im[r*2+k];
                float br = B.re[k*2+c], bi = B.im[k*2+c];
                rr += ar*br - ai*bi;
                ii += ar*bi + ai*br;
            }
            C.re[r*2+c] = rr; C.im[r*2+c] = ii;
        }
    return C;
}
__device__ __forceinline__ C2x2 mk_rx(float t) {
    float c = cosf(0.5f*t), s = sinf(0.5f*t);
    C2x2 M;
    M.re[0]=c;  M.im[0]=0.f;  M.re[1]=0.f; M.im[1]=-s;
    M.re[2]=0.f;M.im[2]=-s;   M.re[3]=c;   M.im[3]=0.f;
    return M;
}
__device__ __forceinline__ C2x2 mk_ry(float t) {
    float c = cosf(0.5f*t), s = sinf(0.5f*t);
    C2x2 M;
    M.re[0]=c;  M.im[0]=0.f;  M.re[1]=-s;  M.im[1]=0.f;
    M.re[2]=s;  M.im[2]=0.f;  M.re[3]=c;   M.im[3]=0.f;
    return M;
}
__device__ __forceinline__ C2x2 mk_u3(float t, float p, float l) {
    float c = cosf(0.5f*t), s = sinf(0.5f*t);
    C2x2 M;
    M.re[0]=c;              M.im[0]=0.f;
    M.re[1]=-cosf(l)*s;     M.im[1]=-sinf(l)*s;
    M.re[2]= cosf(p)*s;     M.im[2]= sinf(p)*s;
    M.re[3]= cosf(p+l)*c;   M.im[3]= sinf(p+l)*c;
    return M;
}

// ---------------------------------------------------------------------------
// Warp-level circuit sim primitives (validated R1)
// ---------------------------------------------------------------------------
__device__ __forceinline__ void apply_gate(const float* __restrict__ gp, int q, int lane,
                                           float& ar0, float& ai0, float& ar1, float& ai1) {
    float4 gA = *(const float4*)gp;
    float4 gB = *(const float4*)(gp + 4);
    if (q == 5) {
        float n0r = gA.x*ar0 - gA.y*ai0 + gA.z*ar1 - gA.w*ai1;
        float n0i = gA.x*ai0 + gA.y*ar0 + gA.z*ai1 + gA.w*ar1;
        float n1r = gB.x*ar0 - gB.y*ai0 + gB.z*ar1 - gB.w*ai1;
        float n1i = gB.x*ai0 + gB.y*ar0 + gB.z*ai1 + gB.w*ar1;
        ar0=n0r; ai0=n0i; ar1=n1r; ai1=n1i;
    } else {
        int sh = 4 - q;
        int lx = 1 << sh;
        int bit = (lane >> sh) & 1;
        float br0 = __shfl_xor_sync(0xffffffffu, ar0, lx);
        float bi0 = __shfl_xor_sync(0xffffffffu, ai0, lx);
        float br1 = __shfl_xor_sync(0xffffffffu, ar1, lx);
        float bi1 = __shfl_xor_sync(0xffffffffu, ai1, lx);
        float csr = bit ? gB.z : gA.x;
        float csi = bit ? gB.w : gA.y;
        float cor = bit ? gB.x : gA.z;
        float coi = bit ? gB.y : gA.w;
        float n0r = csr*ar0 - csi*ai0 + cor*br0 - coi*bi0;
        float n0i = csr*ai0 + csi*ar0 + cor*bi0 + coi*br0;
        float n1r = csr*ar1 - csi*ai1 + cor*br1 - coi*bi1;
        float n1i = csr*ai1 + csi*ar1 + cor*bi1 + coi*br1;
        ar0=n0r; ai0=n0i; ar1=n1r; ai1=n1i;
    }
}

__device__ __forceinline__ void apply_section(const float* __restrict__ sg, int base, int lane,
                                              float& ar0, float& ai0, float& ar1, float& ai1) {
    #pragma unroll
    for (int i = 0; i < 6; i++)
        apply_gate(sg + (base + i) * 8, i, lane, ar0, ai0, ar1, ai1);
}

__device__ __forceinline__ void apply_chain(int lane,
                                            float& ar0, float& ai0, float& ar1, float& ai1) {
    #pragma unroll
    for (int i = 0; i < 4; i++) {
        int lx = 1 << (3 - i);
        int cb = (lane >> (4 - i)) & 1;
        float br0 = __shfl_xor_sync(0xffffffffu, ar0, lx);
        float bi0 = __shfl_xor_sync(0xffffffffu, ai0, lx);
        float br1 = __shfl_xor_sync(0xffffffffu, ar1, lx);
        float bi1 = __shfl_xor_sync(0xffffffffu, ai1, lx);
        if (cb) { ar0=br0; ai0=bi0; ar1=br1; ai1=bi1; }
    }
    {
        int cb = lane & 1;
        float tr = ar0, ti = ai0;
        ar0 = cb ? ar1 : ar0;  ai0 = cb ? ai1 : ai0;
        ar1 = cb ? tr  : ar1;  ai1 = cb ? ti  : ai1;
    }
}

__device__ __forceinline__ float wredsum(float v) {
    #pragma unroll
    for (int o = 16; o > 0; o >>= 1) v += __shfl_xor_sync(0xffffffffu, v, o);
    return v;
}

// ---------------------------------------------------------------------------
// Precompute (R11 config: grid=8 x 256 — validated 17 us)
// ---------------------------------------------------------------------------
__global__ void precompute_kernel(const float* __restrict__ enc_w,
                                  const float* __restrict__ q_w,
                                  const float* __restrict__ k_w,
                                  const float* __restrict__ v_w,
                                  const float* __restrict__ mq,
                                  const float* __restrict__ mk,
                                  const float* __restrict__ mv,
                                  const float* __restrict__ qW,
                                  const float* __restrict__ kW,
                                  const float* __restrict__ raw_tau) {
    __shared__ __align__(16) float sg[576];
    int tid = threadIdx.x;

    if (tid < 72) {
        int g = tid;
        const float* w; const float* mw = nullptr;
        int sec, i; bool is_enc;
        if (g < 18) { w = enc_w; sec = g/6; i = g%6; is_enc = true; }
        else {
            int gg = g - 18; int xq = gg/18; sec = (gg%18)/6; i = gg%6; is_enc = false;
            w  = (xq==0) ? q_w : (xq==1) ? k_w : v_w;
            mw = (xq==0) ? mq  : (xq==1) ? mk  : mv;
        }
        C2x2 G;
        if (sec == 0)      G = cmul(mk_ry(w[i*3+1]), mk_rx(w[i*3+0]));
        else if (sec == 1) G = cmul(cmul(mk_ry(w[18+i*3+1]), mk_rx(w[18+i*3+0])),
                                    mk_ry(w[i*3+2]));
        else {
            if (is_enc) G = mk_ry(w[18+i*3+2]);
            else        G = cmul(mk_u3(mw[i*3+0], mw[i*3+1], mw[i*3+2]),
                                 mk_ry(w[18+i*3+2]));
        }
        float* o = &sg[g*8];
        o[0]=G.re[0]; o[1]=G.im[0]; o[2]=G.re[1]; o[3]=G.im[1];
        o[4]=G.re[2]; o[5]=G.im[2]; o[6]=G.re[3]; o[7]=G.im[3];
    }

    if (blockIdx.x == 0) {
        if (tid == 200) {
            float tau = log1pf(expf(raw_tau[0])) + 1e-9f;
            g_c2 = -1.4426950408889634f / tau;
        }
        for (int e = tid; e < 512; e += 256) {
            int br = e >> 8, j = (e >> 6) & 3, a = e & 63;
            const float* w = br ? kW : qW;
            float acc = 0.f;
            #pragma unroll
            for (int i = 0; i < 6; i++) {
                float sgn = ((a >> (5 - i)) & 1) ? -1.f : 1.f;
                acc += w[j*6 + i] * sgn;
            }
            g_WZ[e] = acc;
        }
    }
    __syncthreads();

    int lane = tid & 31, warp = tid >> 5;
    int c = blockIdx.x * 8 + warp;

    float ar0 = (2*lane     == c) ? 1.f : 0.f;
    float ar1 = (2*lane + 1 == c) ? 1.f : 0.f;
    float ai0 = 0.f, ai1 = 0.f;

    apply_section(sg, 0,  lane, ar0, ai0, ar1, ai1);
    apply_chain(lane, ar0, ai0, ar1, ai1);
    apply_section(sg, 6,  lane, ar0, ai0, ar1, ai1);
    apply_chain(lane, ar0, ai0, ar1, ai1);
    apply_section(sg, 12, lane, ar0, ai0, ar1, ai1);

    float cr0 = ar0, ci0 = ai0, cr1 = ar1, ci1 = ai1;

    #pragma unroll
    for (int br = 0; br < 3; br++) {
        ar0 = cr0; ai0 = ci0; ar1 = cr1; ai1 = ci1;
        int gb = 18 + br * 18;
        apply_section(sg, gb,      lane, ar0, ai0, ar1, ai1);
        apply_chain(lane, ar0, ai0, ar1, ai1);
        apply_section(sg, gb + 6,  lane, ar0, ai0, ar1, ai1);
        apply_chain(lane, ar0, ai0, ar1, ai1);
        apply_section(sg, gb + 12, lane, ar0, ai0, ar1, ai1);

        float* base = &g_M[(br * 64 + c) * 128];
        *(float2*)&base[2*lane]      = make_float2(ar0, ar1);
        *(float2*)&base[64 + 2*lane] = make_float2(ai0, ai1);
    }
}

// ---------------------------------------------------------------------------
// f32x2 helpers (phase1)
// ---------------------------------------------------------------------------
__device__ __forceinline__ u64 pk2(float x) {
    u64 r; asm("mov.b64 %0, {%1, %1};" : "=l"(r) : "f"(x)); return r;
}
__device__ __forceinline__ void fma2(u64& d, u64 a, u64 b) {
    asm("fma.rn.f32x2 %0, %1, %2, %0;" : "+l"(d) : "l"(a), "l"(b));
}
__device__ __forceinline__ float ex2f(float x) {
    float y; asm("ex2.approx.ftz.f32 %0, %1;" : "=f"(y) : "f"(x)); return y;
}

// ---------------------------------------------------------------------------
// Phase 1 (unchanged — validated)
// ---------------------------------------------------------------------------
#define SX_STRIDE 68
#define VT_STRIDE 66
#define P1_SMEM_FLOATS (64*SX_STRIDE + 8320 + 64 + 512 + 16 + (64*VT_STRIDE)/2)

__global__ __launch_bounds__(256) void phase1_kernel(
    const float* __restrict__ x, const float* __restrict__ inp_scale,
    const float* __restrict__ qB, const float* __restrict__ kB,
    const float* __restrict__ lng, const float* __restrict__ lnb) {

    extern __shared__ __align__(16) float sm[];
    float* sX   = sm;
    float* sM   = sX + 64*SX_STRIDE;
    float* sC   = sM;
    float* sInv = sM + 8320;
    float* sWZ  = sInv + 64;
    float* sLN  = sWZ + 512;
    __half* sVT = (__half*)(sLN + 16);

    int tid = threadIdx.x;
    int lane = tid & 31, warp = tid >> 5;
    int tok0 = blockIdx.x * 64;

    {
        int t = tid & 63, cg = tid >> 6;
        const float4* xg = (const float4*)(x + (size_t)(tok0 + t) * 64 + cg * 16);
        #pragma unroll
        for (int i = 0; i < 4; i++) {
            float4 v = xg[i];
            int c = cg * 16 + i * 4;
            float4 sv = *(const float4*)(inp_scale + c);
            sX[(c+0)*SX_STRIDE + t] = v.x * sv.x;
            sX[(c+1)*SX_STRIDE + t] = v.y * sv.y;
            sX[(c+2)*SX_STRIDE + t] = v.z * sv.z;
            sX[(c+3)*SX_STRIDE + t] = v.w * sv.w;
        }
    }
    if (tid < 16)  sLN[tid] = (tid < 4) ? qB[tid] : (tid < 8) ? kB[tid-4]
                             : (tid < 12) ? lng[tid-8] : lnb[tid-12];
    for (int e = tid; e < 512; e += 256) sWZ[e] = g_WZ[e];
    __syncthreads();

    #pragma unroll
    for (int it = 0; it < 8; it++) {
        int t = it * 8 + warp;
        float a0 = sX[lane*SX_STRIDE + t];
        float a1 = sX[(lane+32)*SX_STRIDE + t];
        float s = wredsum(a0*a0 + a1*a1);
        if (lane == 0) {
            float nr = sqrtf(s) + 1e-9f;
            sInv[t] = 1.f / (nr * nr);
        }
    }

    int rg = tid & 15, tg = tid >> 4;
    int r0 = rg * 8, t0 = tg * 4;

    for (int br = 0; br < 3; br++) {
        __syncthreads();
        {
            const float4* mg = (const float4*)&g_M[br * 64 * 128];
            float4* ms = (float4*)sM;
            #pragma unroll
            for (int i = 0; i < 8; i++) ms[i * 256 + tid] = mg[i * 256 + tid];
        }
        __syncthreads();

        u64 acc[4][4] = {};
        #pragma unroll 4
        for (int k = 0; k < 64; k++) {
            ulonglong2 mA = *(const ulonglong2*)&sM[k*128 + r0];
            ulonglong2 mB = *(const ulonglong2*)&sM[k*128 + r0 + 4];
            float4 xv = *(const float4*)&sX[k*SX_STRIDE + t0];
            u64 x0 = pk2(xv.x), x1 = pk2(xv.y), x2 = pk2(xv.z), x3 = pk2(xv.w);
            fma2(acc[0][0], mA.x, x0); fma2(acc[0][1], mA.x, x1);
            fma2(acc[0][2], mA.x, x2); fma2(acc[0][3], mA.x, x3);
            fma2(acc[1][0], mA.y, x0); fma2(acc[1][1], mA.y, x1);
            fma2(acc[1][2], mA.y, x2); fma2(acc[1][3], mA.y, x3);
            fma2(acc[2][0], mB.x, x0); fma2(acc[2][1], mB.x, x1);
            fma2(acc[2][2], mB.x, x2); fma2(acc[2][3], mB.x, x3);
            fma2(acc[3][0], mB.y, x0); fma2(acc[3][1], mB.y, x1);
            fma2(acc[3][2], mB.y, x2); fma2(acc[3][3], mB.y, x3);
        }
        __syncthreads();
        #pragma unroll
        for (int j = 0; j < 4; j++)
            #pragma unroll
            for (int i = 0; i < 4; i++)
                *(u64*)&sC[(t0+j)*130 + r0 + 2*i] = acc[i][j];
        __syncthreads();

        if (br < 2) {
            float2 wz0 = *(float2*)&sWZ[br*256 +   0 + 2*lane];
            float2 wz1 = *(float2*)&sWZ[br*256 +  64 + 2*lane];
            float2 wz2 = *(float2*)&sWZ[br*256 + 128 + 2*lane];
            float2 wz3 = *(float2*)&sWZ[br*256 + 192 + 2*lane];
            #pragma unroll
            for (int it = 0; it < 8; it++) {
                int t = it * 8 + warp;
                float inv = sInv[t];
                float2 re = *(float2*)&sC[t*130 + 2*lane];
                float2 im = *(float2*)&sC[t*130 + 64 + 2*lane];
                float p0 = (re.x*re.x + im.x*im.x) * inv;
                float p1 = (re.y*re.y + im.y*im.y) * inv;
                float o0 = wredsum(p0*wz0.x + p1*wz0.y);
                float o1 = wredsum(p0*wz1.x + p1*wz1.y);
                float o2 = wredsum(p0*wz2.x + p1*wz2.y);
                float o3 = wredsum(p0*wz3.x + p1*wz3.y);
                if (lane == 0) {
                    float o[4];
                    o[0] = o0 + sLN[br*4+0]; o[1] = o1 + sLN[br*4+1];
                    o[2] = o2 + sLN[br*4+2]; o[3] = o3 + sLN[br*4+3];
                    float m = 0.25f * (o[0]+o[1]+o[2]+o[3]);
                    float var = 0.f;
                    #pragma unroll
                    for (int j = 0; j < 4; j++) { float d = o[j]-m; var += d*d; }
                    var *= 0.25f;
                    float rstd = rsqrtf(var + 1e-5f);
                    float r[4], qq = 0.f;
                    #pragma unroll
                    for (int j = 0; j < 4; j++) {
                        r[j] = (o[j]-m)*rstd*sLN[8+j] + sLN[12+j];
                        qq += r[j]*r[j];
                    }
                    int token = tok0 + t;
                    if (br == 0) {
                        g_q[token] = make_float4(r[0], r[1], r[2], r[3]);
                        g_qq[token] = qq;
                    } else {
                        float c2l = g_c2;
                        float s2 = -2.f * c2l;
                        g_k[token] = make_float4(r[0]*s2, r[1]*s2, r[2]*s2, r[3]*s2);
                        g_kk[token] = c2l * qq;
                    }
                }
            }
        } else {
            #pragma unroll
            for (int it = 0; it < 8; it++) {
                int t = it * 8 + warp;
                float inv = sInv[t];
                float2 re = *(float2*)&sC[t*130 + 2*lane];
                float2 im = *(float2*)&sC[t*130 + 64 + 2*lane];
                float p0 = (re.x*re.x + im.x*im.x) * inv;
                float p1 = (re.y*re.y + im.y*im.y) * inv;
                float s1 = wredsum(p0 + p1);
                float s2 = wredsum(p0*p0 + p1*p1);
                float m   = s1 * (1.f/64.f);
                float var = s2 * (1.f/64.f) - m*m;
                float rstd = rsqrtf(var + 1e-5f);
                sVT[(2*lane)   * VT_STRIDE + t] = __float2half((p0 - m) * rstd);
                sVT[(2*lane+1) * VT_STRIDE + t] = __float2half((p1 - m) * rstd);
            }
        }
    }

    __syncthreads();
    {
        int bb = tok0 >> 11, s0 = tok0 & 2047;
        #pragma unroll
        for (int e = tid; e < 2048; e += 256) {
            int dim = e >> 5, i = e & 31;
            __half2 val = *(__half2*)&sVT[dim * VT_STRIDE + 2*i];
            *(__half2*)&g_vt[((size_t)bb * 64 + dim) * SEQ + s0 + 2*i] = val;
        }
    }
}

// ---------------------------------------------------------------------------
// Phase 2: FA2 + alpha pipelined one chunk ahead + 4 V buffers with
// stage-two-ahead so __syncthreads fires only every OTHER chunk. (R11)
// ---------------------------------------------------------------------------
__device__ __forceinline__ uint32_t smem_to_u32(const void* p) {
    uint32_t a;
    asm("{ .reg .u64 t; cvta.to.shared.u64 t, %1; cvt.u32.u64 %0, t; }"
        : "=r"(a) : "l"(p));
    return a;
}

#define LDSM_X4(r, a) \
    asm volatile("ldmatrix.sync.aligned.m8n8.x4.shared.b16 {%0,%1,%2,%3}, [%4];" \
                 : "=r"((r)[0]), "=r"((r)[1]), "=r"((r)[2]), "=r"((r)[3]) : "r"(a))

__device__ __forceinline__ void mma_f16(float* d, const uint32_t* a, const uint32_t* b) {
    asm volatile(
        "mma.sync.aligned.m16n8k16.row.col.f32.f16.f16.f32 "
        "{%0,%1,%2,%3}, {%4,%5,%6,%7}, {%8,%9}, {%0,%1,%2,%3};"
        : "+f"(d[0]), "+f"(d[1]), "+f"(d[2]), "+f"(d[3])
        : "r"(a[0]), "r"(a[1]), "r"(a[2]), "r"(a[3]), "r"(b[0]), "r"(b[1]));
}

// alpha fragments for one 64-key chunk (kk via one LDG.64)
__device__ __forceinline__ void alpha_chunk(
    int kb, int l3, const float4& q0, const float4& q1,
    float qs0, float qs1, uint32_t Af[4][4], float& d0, float& d1) {
    #pragma unroll
    for (int kf = 0; kf < 4; kf++) {
        int kidx = kb + kf * 16 + l3 * 2;
        #pragma unroll
        for (int cc = 0; cc < 2; cc++) {
            int ki = kidx + cc * 8;
            float4 ka = g_k[ki];
            float4 kb4 = g_k[ki + 1];
            float2 kk2 = *(const float2*)&g_kk[ki];
            float e00 = qs0 + kk2.x + ka.x*q0.x + ka.y*q0.y + ka.z*q0.z + ka.w*q0.w;
            float e01 = qs0 + kk2.y + kb4.x*q0.x + kb4.y*q0.y + kb4.z*q0.z + kb4.w*q0.w;
            float e10 = qs1 + kk2.x + ka.x*q1.x + ka.y*q1.y + ka.z*q1.z + ka.w*q1.w;
            float e11 = qs1 + kk2.y + kb4.x*q1.x + kb4.y*q1.y + kb4.z*q1.z + kb4.w*q1.w;
            float a00 = ex2f(fminf(e00, 0.f));
            float a01 = ex2f(fminf(e01, 0.f));
            float a10 = ex2f(fminf(e10, 0.f));
            float a11 = ex2f(fminf(e11, 0.f));
            d0 += a00 + a01;
            d1 += a10 + a11;
            __half2 h0 = __floats2half2_rn(a00, a01);
            __half2 h1 = __floats2half2_rn(a10, a11);
            Af[kf][cc*2 + 0] = *(uint32_t*)&h0;
            Af[kf][cc*2 + 1] = *(uint32_t*)&h1;
        }
    }
}

#define OFF_QV   0        // 2048
#define OFF_QQ   2048     // 512
#define OFF_B0   4096     // 4 buffers x 8192
#define P2_SMEM  36864

__global__ __launch_bounds__(256, 2) void phase2_mma_kernel(float* __restrict__ out) {
    extern __shared__ __align__(1024) char smem[];
    uint32_t sbase = smem_to_u32(smem);
    int tid = threadIdx.x, lane = tid & 31, w = tid >> 5;
    int b = blockIdx.y;
    int qbase = b * SEQ + blockIdx.x * 128;

    float4* qv = (float4*)(smem + OFF_QV);
    float*  qq = (float*)(smem + OFF_QQ);

    if (tid < 128) { qv[tid] = g_q[qbase + tid]; qq[tid] = g_qq[qbase + tid]; }

    const __half* vt_base = g_vt + (size_t)b * 64 * SEQ;

    int vd0 = tid >> 3,         vo0 = tid & 7;
    int vd1 = (tid + 256) >> 3, vo1 = tid & 7;
    uint32_t voff0 = vd0 * 128 + ((vo0 ^ (vd0 & 7)) * 16);
    uint32_t voff1 = vd1 * 128 + ((vo1 ^ (vd1 & 7)) * 16);

    // prologue: fill buf0 (chunk 0) and buf1 (chunk 1); prefetch chunk 2
    {
        uint4 a0 = *(const uint4*)(vt_base + (size_t)vd0 * SEQ + vo0 * 8);
        uint4 a1 = *(const uint4*)(vt_base + (size_t)vd1 * SEQ + vo1 * 8);
        uint4 b0 = *(const uint4*)(vt_base + (size_t)vd0 * SEQ + 64 + vo0 * 8);
        uint4 b1 = *(const uint4*)(vt_base + (size_t)vd1 * SEQ + 64 + vo1 * 8);
        *(uint4*)(smem + OFF_B0 + voff0) = a0;
        *(uint4*)(smem + OFF_B0 + voff1) = a1;
        *(uint4*)(smem + OFF_B0 + 8192 + voff0) = b0;
        *(uint4*)(smem + OFF_B0 + 8192 + voff1) = b1;
    }
    uint4 pv0 = *(const uint4*)(vt_base + (size_t)vd0 * SEQ + 128 + vo0 * 8);
    uint4 pv1 = *(const uint4*)(vt_base + (size_t)vd1 * SEQ + 128 + vo1 * 8);
    __syncthreads();

    int l3 = lane & 3, rloc = lane >> 2;
    int r0 = w * 16 + rloc, r1 = r0 + 8;
    float4 q0 = qv[r0], q1 = qv[r1];
    float c2 = g_c2;
    float qs0 = c2 * qq[r0], qs1 = c2 * qq[r1];

    float d0 = 0.f, d1 = 0.f;
    float acc[8][4] = {};

    int b_rloc = lane & 7;
    int b_cbo  = lane >> 3;

    uint32_t Af[4][4], Afn[4][4];
    alpha_chunk(b * SEQ, l3, q0, q1, qs0, qs1, Af, d0, d1);

    for (int kc = 0; kc < 32; kc++) {
        uint32_t bufR = OFF_B0 + (kc & 3) * 8192;

        // stage chunk kc+2 (prefetched), prefetch chunk kc+3
        if (kc < 30) {
            uint32_t bufW = OFF_B0 + ((kc + 2) & 3) * 8192;
            *(uint4*)(smem + bufW + voff0) = pv0;
            *(uint4*)(smem + bufW + voff1) = pv1;
            if (kc < 29) {
                int kn = (kc + 3) * 64;
                pv0 = *(const uint4*)(vt_base + (size_t)vd0 * SEQ + kn + vo0 * 8);
                pv1 = *(const uint4*)(vt_base + (size_t)vd1 * SEQ + kn + vo1 * 8);
            }
        }
        // alpha for next chunk (independent FFMA/MUFU stream)
        if (kc < 31)
            alpha_chunk(b * SEQ + (kc + 1) * 64, l3, q0, q1, qs0, qs1, Afn, d0, d1);

        // MMA stream for current chunk
        #pragma unroll
        for (int nt = 0; nt < 8; nt++) {
            uint32_t Bh[8];
            int brow = nt * 8 + b_rloc;
            #pragma unroll
            for (int ks2 = 0; ks2 < 2; ks2++) {
                int cb = ks2 * 4 + b_cbo;
                uint32_t addr = sbase + bufR + brow * 128 + ((cb ^ (brow & 7)) * 16);
                LDSM_X4(&Bh[ks2*4], addr);
            }
            #pragma unroll
            for (int kf = 0; kf < 4; kf++)
                mma_f16(acc[nt], Af[kf], &Bh[kf*2]);
        }

        #pragma unroll
        for (int kf = 0; kf < 4; kf++)
            #pragma unroll
            for (int j = 0; j < 4; j++)
                Af[kf][j] = Afn[kf][j];

        if (kc & 1) __syncthreads();   // barrier every OTHER chunk
    }

    d0 += __shfl_xor_sync(0xffffffffu, d0, 1);
    d0 += __shfl_xor_sync(0xffffffffu, d0, 2);
    d1 += __shfl_xor_sync(0xffffffffu, d1, 1);
    d1 += __shfl_xor_sync(0xffffffffu, d1, 2);
    float rdT = 1.f / (d0 + 1e-9f);
    float rdB = 1.f / (d1 + 1e-9f);

    int cl = l3 * 2;
    #pragma unroll
    for (int nt = 0; nt < 8; nt++) {
        *(float2*)&out[(size_t)(qbase + r0) * 64 + nt*8 + cl] =
            make_float2(acc[nt][0] * rdT, acc[nt][1] * rdT);
        *(float2*)&out[(size_t)(qbase + r1) * 64 + nt*8 + cl] =
            make_float2(acc[nt][2] * rdB, acc[nt][3] * rdB);
    }
}

// ---------------------------------------------------------------------------
// Launch
// ---------------------------------------------------------------------------
extern "C" void kernel_launch(void* const* d_in, const int* in_sizes, int n_in,
                              void* d_out, int out_size) {
    const float* x         = (const float*)d_in[0];
    const float* inp_scale = (const float*)d_in[1];
    const float* enc_w     = (const float*)d_in[2];
    const float* q_w       = (const float*)d_in[3];
    const float* k_w       = (const float*)d_in[4];
    const float* v_w       = (const float*)d_in[5];
    const float* mq        = (const float*)d_in[6];
    const float* mk        = (const float*)d_in[7];
    const float* mv        = (const float*)d_in[8];
    const float* qW        = (const float*)d_in[9];
    const float* qB        = (const float*)d_in[10];
    const float* kW        = (const float*)d_in[11];
    const float* kB        = (const float*)d_in[12];
    const float* lng       = (const float*)d_in[13];
    const float* lnb       = (const float*)d_in[14];
    const float* raw_tau   = (const float*)d_in[15];

    static int attr_set = 0;
    const int P1_SMEM = P1_SMEM_FLOATS * 4;
    if (!attr_set) {
        cudaFuncSetAttribute(phase1_kernel,
                             cudaFuncAttributeMaxDynamicSharedMemorySize, P1_SMEM);
        cudaFuncSetAttribute(phase2_mma_kernel,
                             cudaFuncAttributeMaxDynamicSharedMemorySize, P2_SMEM);
        attr_set = 1;
    }

    precompute_kernel<<<8, 256>>>(enc_w, q_w, k_w, v_w, mq, mk, mv, qW, kW, raw_tau);
    phase1_kernel<<<NTOK / 64, 256, P1_SMEM>>>(x, inp_scale, qB, kB, lng, lnb);
    phase2_mma_kernel<<<dim3(SEQ / 128, NBATCH), 256, P2_SMEM>>>((float*)d_out);
}

// round 15
// speedup vs baseline: 1.2380x; 1.0390x over previous
#include <cuda_runtime.h>
#include <cuda_fp16.h>
#include <math.h>
#include <stdint.h>

// ---------------------------------------------------------------------------
// Problem constants: B=16, S=2048, D=64, NQ=6
// ---------------------------------------------------------------------------
#define NTOK   32768
#define SEQ    2048
#define NBATCH 16

typedef unsigned long long u64;

// ---------------------------------------------------------------------------
// Device scratch (static — no allocation)
// ---------------------------------------------------------------------------
static __device__ float  g_M[3 * 64 * 128];
static __device__ float  g_WZ[2 * 4 * 64];
static __device__ float  g_c2;
static __device__ float4 g_q[NTOK];
static __device__ float4 g_k[NTOK];    // pre-scaled: -2*c2*k
static __device__ float  g_qq[NTOK];
static __device__ float  g_kk[NTOK];   // pre-scaled: c2*kk
static __device__ __half g_vt[NBATCH * 64 * SEQ];   // [b][dim][s]  fp16 V^T

// ---------------------------------------------------------------------------
// Gate composition helpers
// ---------------------------------------------------------------------------
struct C2x2 { float re[4]; float im[4]; };

__device__ __forceinline__ C2x2 cmul(const C2x2& A, const C2x2& B) {
    C2x2 C;
    #pragma unroll
    for (int r = 0; r < 2; r++)
        #pragma unroll
        for (int c = 0; c < 2; c++) {
            float rr = 0.f, ii = 0.f;
            #pragma unroll
            for (int k = 0; k < 2; k++) {
                float ar = A.re[r*2+k], ai = A.im[r*2+k];
                float br = B.re[k*2+c], bi = B.im[k*2+c];
                rr += ar*br - ai*bi;
                ii += ar*bi + ai*br;
            }
            C.re[r*2+c] = rr; C.im[r*2+c] = ii;
        }
    return C;
}
__device__ __forceinline__ C2x2 mk_rx(float t) {
    float c = cosf(0.5f*t), s = sinf(0.5f*t);
    C2x2 M;
    M.re[0]=c;  M.im[0]=0.f;  M.re[1]=0.f; M.im[1]=-s;
    M.re[2]=0.f;M.im[2]=-s;   M.re[3]=c;   M.im[3]=0.f;
    return M;
}
__device__ __forceinline__ C2x2 mk_ry(float t) {
    float c = cosf(0.5f*t), s = sinf(0.5f*t);
    C2x2 M;
    M.re[0]=c;  M.im[0]=0.f;  M.re[1]=-s;  M.im[1]=0.f;
    M.re[2]=s;  M.im[2]=0.f;  M.re[3]=c;   M.im[3]=0.f;
    return M;
}
__device__ __forceinline__ C2x2 mk_u3(float t, float p, float l) {
    float c = cosf(0.5f*t), s = sinf(0.5f*t);
    C2x2 M;
    M.re[0]=c;              M.im[0]=0.f;
    M.re[1]=-cosf(l)*s;     M.im[1]=-sinf(l)*s;
    M.re[2]= cosf(p)*s;     M.im[2]= sinf(p)*s;
    M.re[3]= cosf(p+l)*c;   M.im[3]= sinf(p+l)*c;
    return M;
}

// ---------------------------------------------------------------------------
// Warp-level circuit sim primitives (validated R1)
// ---------------------------------------------------------------------------
__device__ __forceinline__ void apply_gate(const float* __restrict__ gp, int q, int lane,
                                           float& ar0, float& ai0, float& ar1, float& ai1) {
    float4 gA = *(const float4*)gp;
    float4 gB = *(const float4*)(gp + 4);
    if (q == 5) {
        float n0r = gA.x*ar0 - gA.y*ai0 + gA.z*ar1 - gA.w*ai1;
        float n0i = gA.x*ai0 + gA.y*ar0 + gA.z*ai1 + gA.w*ar1;
        float n1r = gB.x*ar0 - gB.y*ai0 + gB.z*ar1 - gB.w*ai1;
        float n1i = gB.x*ai0 + gB.y*ar0 + gB.z*ai1 + gB.w*ar1;
        ar0=n0r; ai0=n0i; ar1=n1r; ai1=n1i;
    } else {
        int sh = 4 - q;
        int lx = 1 << sh;
        int bit = (lane >> sh) & 1;
        float br0 = __shfl_xor_sync(0xffffffffu, ar0, lx);
        float bi0 = __shfl_xor_sync(0xffffffffu, ai0, lx);
        float br1 = __shfl_xor_sync(0xffffffffu, ar1, lx);
        float bi1 = __shfl_xor_sync(0xffffffffu, ai1, lx);
        float csr = bit ? gB.z : gA.x;
        float csi = bit ? gB.w : gA.y;
        float cor = bit ? gB.x : gA.z;
        float coi = bit ? gB.y : gA.w;
        float n0r = csr*ar0 - csi*ai0 + cor*br0 - coi*bi0;
        float n0i = csr*ai0 + csi*ar0 + cor*bi0 + coi*br0;
        float n1r = csr*ar1 - csi*ai1 + cor*br1 - coi*bi1;
        float n1i = csr*ai1 + csi*ar1 + cor*bi1 + coi*br1;
        ar0=n0r; ai0=n0i; ar1=n1r; ai1=n1i;
    }
}

__device__ __forceinline__ void apply_section(const float* __restrict__ sg, int base, int lane,
                                              float& ar0, float& ai0, float& ar1, float& ai1) {
    #pragma unroll
    for (int i = 0; i < 6; i++)
        apply_gate(sg + (base + i) * 8, i, lane, ar0, ai0, ar1, ai1);
}

__device__ __forceinline__ void apply_chain(int lane,
                                            float& ar0, float& ai0, float& ar1, float& ai1) {
    #pragma unroll
    for (int i = 0; i < 4; i++) {
        int lx = 1 << (3 - i);
        int cb = (lane >> (4 - i)) & 1;
        float br0 = __shfl_xor_sync(0xffffffffu, ar0, lx);
        float bi0 = __shfl_xor_sync(0xffffffffu, ai0, lx);
        float br1 = __shfl_xor_sync(0xffffffffu, ar1, lx);
        float bi1 = __shfl_xor_sync(0xffffffffu, ai1, lx);
        if (cb) { ar0=br0; ai0=bi0; ar1=br1; ai1=bi1; }
    }
    {
        int cb = lane & 1;
        float tr = ar0, ti = ai0;
        ar0 = cb ? ar1 : ar0;  ai0 = cb ? ai1 : ai0;
        ar1 = cb ? tr  : ar1;  ai1 = cb ? ti  : ai1;
    }
}

__device__ __forceinline__ float wredsum(float v) {
    #pragma unroll
    for (int o = 16; o > 0; o >>= 1) v += __shfl_xor_sync(0xffffffffu, v, o);
    return v;
}

// ---------------------------------------------------------------------------
// Precompute (validated 17 us config)
// ---------------------------------------------------------------------------
__global__ void precompute_kernel(const float* __restrict__ enc_w,
                                  const float* __restrict__ q_w,
                                  const float* __restrict__ k_w,
                                  const float* __restrict__ v_w,
                                  const float* __restrict__ mq,
                                  const float* __restrict__ mk,
                                  const float* __restrict__ mv,
                                  const float* __restrict__ qW,
                                  const float* __restrict__ kW,
                                  const float* __restrict__ raw_tau) {
    __shared__ __align__(16) float sg[576];
    int tid = threadIdx.x;

    if (tid < 72) {
        int g = tid;
        const float* w; const float* mw = nullptr;
        int sec, i; bool is_enc;
        if (g < 18) { w = enc_w; sec = g/6; i = g%6; is_enc = true; }
        else {
            int gg = g - 18; int xq = gg/18; sec = (gg%18)/6; i = gg%6; is_enc = false;
            w  = (xq==0) ? q_w : (xq==1) ? k_w : v_w;
            mw = (xq==0) ? mq  : (xq==1) ? mk  : mv;
        }
        C2x2 G;
        if (sec == 0)      G = cmul(mk_ry(w[i*3+1]), mk_rx(w[i*3+0]));
        else if (sec == 1) G = cmul(cmul(mk_ry(w[18+i*3+1]), mk_rx(w[18+i*3+0])),
                                    mk_ry(w[i*3+2]));
        else {
            if (is_enc) G = mk_ry(w[18+i*3+2]);
            else        G = cmul(mk_u3(mw[i*3+0], mw[i*3+1], mw[i*3+2]),
                                 mk_ry(w[18+i*3+2]));
        }
        float* o = &sg[g*8];
        o[0]=G.re[0]; o[1]=G.im[0]; o[2]=G.re[1]; o[3]=G.im[1];
        o[4]=G.re[2]; o[5]=G.im[2]; o[6]=G.re[3]; o[7]=G.im[3];
    }

    if (blockIdx.x == 0) {
        if (tid == 200) {
            float tau = log1pf(expf(raw_tau[0])) + 1e-9f;
            g_c2 = -1.4426950408889634f / tau;
        }
        for (int e = tid; e < 512; e += 256) {
            int br = e >> 8, j = (e >> 6) & 3, a = e & 63;
            const float* w = br ? kW : qW;
            float acc = 0.f;
            #pragma unroll
            for (int i = 0; i < 6; i++) {
                float sgn = ((a >> (5 - i)) & 1) ? -1.f : 1.f;
                acc += w[j*6 + i] * sgn;
            }
            g_WZ[e] = acc;
        }
    }
    __syncthreads();

    int lane = tid & 31, warp = tid >> 5;
    int c = blockIdx.x * 8 + warp;

    float ar0 = (2*lane     == c) ? 1.f : 0.f;
    float ar1 = (2*lane + 1 == c) ? 1.f : 0.f;
    float ai0 = 0.f, ai1 = 0.f;

    apply_section(sg, 0,  lane, ar0, ai0, ar1, ai1);
    apply_chain(lane, ar0, ai0, ar1, ai1);
    apply_section(sg, 6,  lane, ar0, ai0, ar1, ai1);
    apply_chain(lane, ar0, ai0, ar1, ai1);
    apply_section(sg, 12, lane, ar0, ai0, ar1, ai1);

    float cr0 = ar0, ci0 = ai0, cr1 = ar1, ci1 = ai1;

    #pragma unroll
    for (int br = 0; br < 3; br++) {
        ar0 = cr0; ai0 = ci0; ar1 = cr1; ai1 = ci1;
        int gb = 18 + br * 18;
        apply_section(sg, gb,      lane, ar0, ai0, ar1, ai1);
        apply_chain(lane, ar0, ai0, ar1, ai1);
        apply_section(sg, gb + 6,  lane, ar0, ai0, ar1, ai1);
        apply_chain(lane, ar0, ai0, ar1, ai1);
        apply_section(sg, gb + 12, lane, ar0, ai0, ar1, ai1);

        float* base = &g_M[(br * 64 + c) * 128];
        *(float2*)&base[2*lane]      = make_float2(ar0, ar1);
        *(float2*)&base[64 + 2*lane] = make_float2(ai0, ai1);
    }
}

// ---------------------------------------------------------------------------
// f32x2 helpers (phase1)
// ---------------------------------------------------------------------------
__device__ __forceinline__ u64 pk2(float x) {
    u64 r; asm("mov.b64 %0, {%1, %1};" : "=l"(r) : "f"(x)); return r;
}
__device__ __forceinline__ void fma2(u64& d, u64 a, u64 b) {
    asm("fma.rn.f32x2 %0, %1, %2, %0;" : "+l"(d) : "l"(a), "l"(b));
}
__device__ __forceinline__ float ex2f(float x) {
    float y; asm("ex2.approx.ftz.f32 %0, %1;" : "=f"(y) : "f"(x)); return y;
}

// ---------------------------------------------------------------------------
// Phase 1: main GEMM unchanged; Q/K epilogue now a small WZ-GEMM over smem
// instead of per-token warp reductions. smem layout (floats):
//   sX  64*68 | sMC 8320 | sInv 64 | sWZ 512 | sLN 16
//   sPV 64*65 (union: sP fp32 [a][t] for Q/K, sVT fp16 [dim][t] for V)
//   sO  4*64
// ---------------------------------------------------------------------------
#define SX_STRIDE 68
#define VT_STRIDE 66
#define SP_STRIDE 65
#define P1_SMEM_FLOATS (64*SX_STRIDE + 8320 + 64 + 512 + 16 + 64*SP_STRIDE + 4*64)

__global__ __launch_bounds__(256) void phase1_kernel(
    const float* __restrict__ x, const float* __restrict__ inp_scale,
    const float* __restrict__ qB, const float* __restrict__ kB,
    const float* __restrict__ lng, const float* __restrict__ lnb) {

    extern __shared__ __align__(16) float sm[];
    float* sX   = sm;
    float* sM   = sX + 64*SX_STRIDE;
    float* sC   = sM;
    float* sInv = sM + 8320;
    float* sWZ  = sInv + 64;
    float* sLN  = sWZ + 512;
    float* sP   = sLN + 16;               // 64*65 fp32 (Q/K)
    __half* sVT = (__half*)sP;            // fp16 [dim][t] stride 66 (V) — union
    float* sO   = sP + 64*SP_STRIDE;      // 4*64

    int tid = threadIdx.x;
    int lane = tid & 31, warp = tid >> 5;
    int tok0 = blockIdx.x * 64;

    {
        int t = tid & 63, cg = tid >> 6;
        const float4* xg = (const float4*)(x + (size_t)(tok0 + t) * 64 + cg * 16);
        #pragma unroll
        for (int i = 0; i < 4; i++) {
            float4 v = xg[i];
            int c = cg * 16 + i * 4;
            float4 sv = *(const float4*)(inp_scale + c);
            sX[(c+0)*SX_STRIDE + t] = v.x * sv.x;
            sX[(c+1)*SX_STRIDE + t] = v.y * sv.y;
            sX[(c+2)*SX_STRIDE + t] = v.z * sv.z;
            sX[(c+3)*SX_STRIDE + t] = v.w * sv.w;
        }
    }
    if (tid < 16)  sLN[tid] = (tid < 4) ? qB[tid] : (tid < 8) ? kB[tid-4]
                             : (tid < 12) ? lng[tid-8] : lnb[tid-12];
    for (int e = tid; e < 512; e += 256) sWZ[e] = g_WZ[e];
    __syncthreads();

    #pragma unroll
    for (int it = 0; it < 8; it++) {
        int t = it * 8 + warp;
        float a0 = sX[lane*SX_STRIDE + t];
        float a1 = sX[(lane+32)*SX_STRIDE + t];
        float s = wredsum(a0*a0 + a1*a1);
        if (lane == 0) {
            float nr = sqrtf(s) + 1e-9f;
            sInv[t] = 1.f / (nr * nr);
        }
    }

    int rg = tid & 15, tg = tid >> 4;
    int r0 = rg * 8, t0 = tg * 4;

    for (int br = 0; br < 3; br++) {
        __syncthreads();
        {
            const float4* mg = (const float4*)&g_M[br * 64 * 128];
            float4* ms = (float4*)sM;
            #pragma unroll
            for (int i = 0; i < 8; i++) ms[i * 256 + tid] = mg[i * 256 + tid];
        }
        __syncthreads();

        u64 acc[4][4] = {};
        #pragma unroll 4
        for (int k = 0; k < 64; k++) {
            ulonglong2 mA = *(const ulonglong2*)&sM[k*128 + r0];
            ulonglong2 mB = *(const ulonglong2*)&sM[k*128 + r0 + 4];
            float4 xv = *(const float4*)&sX[k*SX_STRIDE + t0];
            u64 x0 = pk2(xv.x), x1 = pk2(xv.y), x2 = pk2(xv.z), x3 = pk2(xv.w);
            fma2(acc[0][0], mA.x, x0); fma2(acc[0][1], mA.x, x1);
            fma2(acc[0][2], mA.x, x2); fma2(acc[0][3], mA.x, x3);
            fma2(acc[1][0], mA.y, x0); fma2(acc[1][1], mA.y, x1);
            fma2(acc[1][2], mA.y, x2); fma2(acc[1][3], mA.y, x3);
            fma2(acc[2][0], mB.x, x0); fma2(acc[2][1], mB.x, x1);
            fma2(acc[2][2], mB.x, x2); fma2(acc[2][3], mB.x, x3);
            fma2(acc[3][0], mB.y, x0); fma2(acc[3][1], mB.y, x1);
            fma2(acc[3][2], mB.y, x2); fma2(acc[3][3], mB.y, x3);
        }
        __syncthreads();
        #pragma unroll
        for (int j = 0; j < 4; j++)
            #pragma unroll
            for (int i = 0; i < 4; i++)
                *(u64*)&sC[(t0+j)*130 + r0 + 2*i] = acc[i][j];
        __syncthreads();

        if (br < 2) {
            // build sP[a][t] = probability
            #pragma unroll
            for (int it = 0; it < 8; it++) {
                int t = it * 8 + warp;
                float inv = sInv[t];
                float2 re = *(float2*)&sC[t*130 + 2*lane];
                float2 im = *(float2*)&sC[t*130 + 64 + 2*lane];
                sP[(2*lane)  *SP_STRIDE + t] = (re.x*re.x + im.x*im.x) * inv;
                sP[(2*lane+1)*SP_STRIDE + t] = (re.y*re.y + im.y*im.y) * inv;
            }
            __syncthreads();

            // GEMM2: o[j][t] = bias_j + sum_a WZ[j][a] * P[a][t]
            {
                int j = tid >> 6, t = tid & 63;
                const float* wz = &sWZ[br*256 + j*64];
                float o = sLN[br*4 + j];
                #pragma unroll 8
                for (int a = 0; a < 64; a++)
                    o += wz[a] * sP[a*SP_STRIDE + t];
                sO[j*64 + t] = o;
            }
            __syncthreads();

            // LN + store (64 threads, one per token)
            if (tid < 64) {
                int t = tid;
                float o0 = sO[t], o1 = sO[64+t], o2 = sO[128+t], o3 = sO[192+t];
                float m = 0.25f * (o0+o1+o2+o3);
                float d0=o0-m, d1=o1-m, d2=o2-m, d3=o3-m;
                float var = 0.25f * (d0*d0 + d1*d1 + d2*d2 + d3*d3);
                float rstd = rsqrtf(var + 1e-5f);
                float r0v = d0*rstd*sLN[8]  + sLN[12];
                float r1v = d1*rstd*sLN[9]  + sLN[13];
                float r2v = d2*rstd*sLN[10] + sLN[14];
                float r3v = d3*rstd*sLN[11] + sLN[15];
                float qq = r0v*r0v + r1v*r1v + r2v*r2v + r3v*r3v;
                int token = tok0 + t;
                if (br == 0) {
                    g_q[token] = make_float4(r0v, r1v, r2v, r3v);
                    g_qq[token] = qq;
                } else {
                    float c2l = g_c2;
                    float s2 = -2.f * c2l;
                    g_k[token] = make_float4(r0v*s2, r1v*s2, r2v*s2, r3v*s2);
                    g_kk[token] = c2l * qq;
                }
            }
        } else {
            #pragma unroll
            for (int it = 0; it < 8; it++) {
                int t = it * 8 + warp;
                float inv = sInv[t];
                float2 re = *(float2*)&sC[t*130 + 2*lane];
                float2 im = *(float2*)&sC[t*130 + 64 + 2*lane];
                float p0 = (re.x*re.x + im.x*im.x) * inv;
                float p1 = (re.y*re.y + im.y*im.y) * inv;
                float s1 = wredsum(p0 + p1);
                float s2 = wredsum(p0*p0 + p1*p1);
                float m   = s1 * (1.f/64.f);
                float var = s2 * (1.f/64.f) - m*m;
                float rstd = rsqrtf(var + 1e-5f);
                sVT[(2*lane)   * VT_STRIDE + t] = __float2half((p0 - m) * rstd);
                sVT[(2*lane+1) * VT_STRIDE + t] = __float2half((p1 - m) * rstd);
            }
        }
    }

    __syncthreads();
    {
        int bb = tok0 >> 11, s0 = tok0 & 2047;
        #pragma unroll
        for (int e = tid; e < 2048; e += 256) {
            int dim = e >> 5, i = e & 31;
            __half2 val = *(__half2*)&sVT[dim * VT_STRIDE + 2*i];
            *(__half2*)&g_vt[((size_t)bb * 64 + dim) * SEQ + s0 + 2*i] = val;
        }
    }
}

// ---------------------------------------------------------------------------
// Phase 2: FA2 + alpha pipelined one chunk ahead + 4 V buffers with
// stage-two-ahead so __syncthreads fires only every OTHER chunk. (R11 exact)
// ---------------------------------------------------------------------------
__device__ __forceinline__ uint32_t smem_to_u32(const void* p) {
    uint32_t a;
    asm("{ .reg .u64 t; cvta.to.shared.u64 t, %1; cvt.u32.u64 %0, t; }"
        : "=r"(a) : "l"(p));
    return a;
}

#define LDSM_X4(r, a) \
    asm volatile("ldmatrix.sync.aligned.m8n8.x4.shared.b16 {%0,%1,%2,%3}, [%4];" \
                 : "=r"((r)[0]), "=r"((r)[1]), "=r"((r)[2]), "=r"((r)[3]) : "r"(a))

__device__ __forceinline__ void mma_f16(float* d, const uint32_t* a, const uint32_t* b) {
    asm volatile(
        "mma.sync.aligned.m16n8k16.row.col.f32.f16.f16.f32 "
        "{%0,%1,%2,%3}, {%4,%5,%6,%7}, {%8,%9}, {%0,%1,%2,%3};"
        : "+f"(d[0]), "+f"(d[1]), "+f"(d[2]), "+f"(d[3])
        : "r"(a[0]), "r"(a[1]), "r"(a[2]), "r"(a[3]), "r"(b[0]), "r"(b[1]));
}

__device__ __forceinline__ void alpha_chunk(
    int kb, int l3, const float4& q0, const float4& q1,
    float qs0, float qs1, uint32_t Af[4][4], float& d0, float& d1) {
    #pragma unroll
    for (int kf = 0; kf < 4; kf++) {
        int kidx = kb + kf * 16 + l3 * 2;
        #pragma unroll
        for (int cc = 0; cc < 2; cc++) {
            int ki = kidx + cc * 8;
            float4 ka = g_k[ki];
            float4 kb4 = g_k[ki + 1];
            float2 kk2 = *(const float2*)&g_kk[ki];
            float e00 = qs0 + kk2.x + ka.x*q0.x + ka.y*q0.y + ka.z*q0.z + ka.w*q0.w;
            float e01 = qs0 + kk2.y + kb4.x*q0.x + kb4.y*q0.y + kb4.z*q0.z + kb4.w*q0.w;
            float e10 = qs1 + kk2.x + ka.x*q1.x + ka.y*q1.y + ka.z*q1.z + ka.w*q1.w;
            float e11 = qs1 + kk2.y + kb4.x*q1.x + kb4.y*q1.y + kb4.z*q1.z + kb4.w*q1.w;
            float a00 = ex2f(fminf(e00, 0.f));
            float a01 = ex2f(fminf(e01, 0.f));
            float a10 = ex2f(fminf(e10, 0.f));
            float a11 = ex2f(fminf(e11, 0.f));
            d0 += a00 + a01;
            d1 += a10 + a11;
            __half2 h0 = __floats2half2_rn(a00, a01);
            __half2 h1 = __floats2half2_rn(a10, a11);
            Af[kf][cc*2 + 0] = *(uint32_t*)&h0;
            Af[kf][cc*2 + 1] = *(uint32_t*)&h1;
        }
    }
}

#define OFF_QV   0        // 2048
#define OFF_QQ   2048     // 512
#define OFF_B0   4096     // 4 buffers x 8192
#define P2_SMEM  36864

__global__ __launch_bounds__(256, 2) void phase2_mma_kernel(float* __restrict__ out) {
    extern __shared__ __align__(1024) char smem[];
    uint32_t sbase = smem_to_u32(smem);
    int tid = threadIdx.x, lane = tid & 31, w = tid >> 5;
    int b = blockIdx.y;
    int qbase = b * SEQ + blockIdx.x * 128;

    float4* qv = (float4*)(smem + OFF_QV);
    float*  qq = (float*)(smem + OFF_QQ);

    if (tid < 128) { qv[tid] = g_q[qbase + tid]; qq[tid] = g_qq[qbase + tid]; }

    const __half* vt_base = g_vt + (size_t)b * 64 * SEQ;

    int vd0 = tid >> 3,         vo0 = tid & 7;
    int vd1 = (tid + 256) >> 3, vo1 = tid & 7;
    uint32_t voff0 = vd0 * 128 + ((vo0 ^ (vd0 & 7)) * 16);
    uint32_t voff1 = vd1 * 128 + ((vo1 ^ (vd1 & 7)) * 16);

    {
        uint4 a0 = *(const uint4*)(vt_base + (size_t)vd0 * SEQ + vo0 * 8);
        uint4 a1 = *(const uint4*)(vt_base + (size_t)vd1 * SEQ + vo1 * 8);
        uint4 b0 = *(const uint4*)(vt_base + (size_t)vd0 * SEQ + 64 + vo0 * 8);
        uint4 b1 = *(const uint4*)(vt_base + (size_t)vd1 * SEQ + 64 + vo1 * 8);
        *(uint4*)(smem + OFF_B0 + voff0) = a0;
        *(uint4*)(smem + OFF_B0 + voff1) = a1;
        *(uint4*)(smem + OFF_B0 + 8192 + voff0) = b0;
        *(uint4*)(smem + OFF_B0 + 8192 + voff1) = b1;
    }
    uint4 pv0 = *(const uint4*)(vt_base + (size_t)vd0 * SEQ + 128 + vo0 * 8);
    uint4 pv1 = *(const uint4*)(vt_base + (size_t)vd1 * SEQ + 128 + vo1 * 8);
    __syncthreads();

    int l3 = lane & 3, rloc = lane >> 2;
    int r0 = w * 16 + rloc, r1 = r0 + 8;
    float4 q0 = qv[r0], q1 = qv[r1];
    float c2 = g_c2;
    float qs0 = c2 * qq[r0], qs1 = c2 * qq[r1];

    float d0 = 0.f, d1 = 0.f;
    float acc[8][4] = {};

    int b_rloc = lane & 7;
    int b_cbo  = lane >> 3;

    uint32_t Af[4][4], Afn[4][4];
    alpha_chunk(b * SEQ, l3, q0, q1, qs0, qs1, Af, d0, d1);

    for (int kc = 0; kc < 32; kc++) {
        uint32_t bufR = OFF_B0 + (kc & 3) * 8192;

        if (kc < 30) {
            uint32_t bufW = OFF_B0 + ((kc + 2) & 3) * 8192;
            *(uint4*)(smem + bufW + voff0) = pv0;
            *(uint4*)(smem + bufW + voff1) = pv1;
            if (kc < 29) {
                int kn = (kc + 3) * 64;
                pv0 = *(const uint4*)(vt_base + (size_t)vd0 * SEQ + kn + vo0 * 8);
                pv1 = *(const uint4*)(vt_base + (size_t)vd1 * SEQ + kn + vo1 * 8);
            }
        }
        if (kc < 31)
            alpha_chunk(b * SEQ + (kc + 1) * 64, l3, q0, q1, qs0, qs1, Afn, d0, d1);

        #pragma unroll
        for (int nt = 0; nt < 8; nt++) {
            uint32_t Bh[8];
            int brow = nt * 8 + b_rloc;
            #pragma unroll
            for (int ks2 = 0; ks2 < 2; ks2++) {
                int cb = ks2 * 4 + b_cbo;
                uint32_t addr = sbase + bufR + brow * 128 + ((cb ^ (brow & 7)) * 16);
                LDSM_X4(&Bh[ks2*4], addr);
            }
            #pragma unroll
            for (int kf = 0; kf < 4; kf++)
                mma_f16(acc[nt], Af[kf], &Bh[kf*2]);
        }

        #pragma unroll
        for (int kf = 0; kf < 4; kf++)
            #pragma unroll
            for (int j = 0; j < 4; j++)
                Af[kf][j] = Afn[kf][j];

        if (kc & 1) __syncthreads();
    }

    d0 += __shfl_xor_sync(0xffffffffu, d0, 1);
    d0 += __shfl_xor_sync(0xffffffffu, d0, 2);
    d1 += __shfl_xor_sync(0xffffffffu, d1, 1);
    d1 += __shfl_xor_sync(0xffffffffu, d1, 2);
    float rdT = 1.f / (d0 + 1e-9f);
    float rdB = 1.f / (d1 + 1e-9f);

    int cl = l3 * 2;
    #pragma unroll
    for (int nt = 0; nt < 8; nt++) {
        *(float2*)&out[(size_t)(qbase + r0) * 64 + nt*8 + cl] =
            make_float2(acc[nt][0] * rdT, acc[nt][1] * rdT);
        *(float2*)&out[(size_t)(qbase + r1) * 64 + nt*8 + cl] =
            make_float2(acc[nt][2] * rdB, acc[nt][3] * rdB);
    }
}

// ---------------------------------------------------------------------------
// Launch
// ---------------------------------------------------------------------------
extern "C" void kernel_launch(void* const* d_in, const int* in_sizes, int n_in,
                              void* d_out, int out_size) {
    const float* x         = (const float*)d_in[0];
    const float* inp_scale = (const float*)d_in[1];
    const float* enc_w     = (const float*)d_in[2];
    const float* q_w       = (const float*)d_in[3];
    const float* k_w       = (const float*)d_in[4];
    const float* v_w       = (const float*)d_in[5];
    const float* mq        = (const float*)d_in[6];
    const float* mk        = (const float*)d_in[7];
    const float* mv        = (const float*)d_in[8];
    const float* qW        = (const float*)d_in[9];
    const float* qB        = (const float*)d_in[10];
    const float* kW        = (const float*)d_in[11];
    const float* kB        = (const float*)d_in[12];
    const float* lng       = (const float*)d_in[13];
    const float* lnb       = (const float*)d_in[14];
    const float* raw_tau   = (const float*)d_in[15];

    static int attr_set = 0;
    const int P1_SMEM = P1_SMEM_FLOATS * 4;
    if (!attr_set) {
        cudaFuncSetAttribute(phase1_kernel,
                             cudaFuncAttributeMaxDynamicSharedMemorySize, P1_SMEM);
        cudaFuncSetAttribute(phase2_mma_kernel,
                             cudaFuncAttributeMaxDynamicSharedMemorySize, P2_SMEM);
        attr_set = 1;
    }

    precompute_kernel<<<8, 256>>>(enc_w, q_w, k_w, v_w, mq, mk, mv, qW, kW, raw_tau);
    phase1_kernel<<<NTOK / 64, 256, P1_SMEM>>>(x, inp_scale, qB, kB, lng, lnb);
    phase2_mma_kernel<<<dim3(SEQ / 128, NBATCH), 256, P2_SMEM>>>((float*)d_out);
}

// round 16
// speedup vs baseline: 1.2556x; 1.0142x over previous
#include <cuda_runtime.h>
#include <cuda_fp16.h>
#include <math.h>
#include <stdint.h>

// ---------------------------------------------------------------------------
// Problem constants: B=16, S=2048, D=64, NQ=6
// ---------------------------------------------------------------------------
#define NTOK   32768
#define SEQ    2048
#define NBATCH 16

typedef unsigned long long u64;

// ---------------------------------------------------------------------------
// Device scratch (static — no allocation)
// ---------------------------------------------------------------------------
static __device__ float  g_M[3 * 64 * 128];
static __device__ float  g_WZ[2 * 4 * 64];
static __device__ float  g_c2;
static __device__ float4 g_q[NTOK];
static __device__ float4 g_k[NTOK];    // pre-scaled: -2*c2*k
static __device__ float  g_qq[NTOK];
static __device__ float  g_kk[NTOK];   // pre-scaled: c2*kk
static __device__ __half g_vt[NBATCH * 64 * SEQ];   // [b][dim][s]  fp16 V^T

// ---------------------------------------------------------------------------
// Gate composition helpers
// ---------------------------------------------------------------------------
struct C2x2 { float re[4]; float im[4]; };

__device__ __forceinline__ C2x2 cmul(const C2x2& A, const C2x2& B) {
    C2x2 C;
    #pragma unroll
    for (int r = 0; r < 2; r++)
        #pragma unroll
        for (int c = 0; c < 2; c++) {
            float rr = 0.f, ii = 0.f;
            #pragma unroll
            for (int k = 0; k < 2; k++) {
                float ar = A.re[r*2+k], ai = A.im[r*2+k];
                float br = B.re[k*2+c], bi = B.im[k*2+c];
                rr += ar*br - ai*bi;
                ii += ar*bi + ai*br;
            }
            C.re[r*2+c] = rr; C.im[r*2+c] = ii;
        }
    return C;
}
__device__ __forceinline__ C2x2 mk_rx(float t) {
    float c = cosf(0.5f*t), s = sinf(0.5f*t);
    C2x2 M;
    M.re[0]=c;  M.im[0]=0.f;  M.re[1]=0.f; M.im[1]=-s;
    M.re[2]=0.f;M.im[2]=-s;   M.re[3]=c;   M.im[3]=0.f;
    return M;
}
__device__ __forceinline__ C2x2 mk_ry(float t) {
    float c = cosf(0.5f*t), s = sinf(0.5f*t);
    C2x2 M;
    M.re[0]=c;  M.im[0]=0.f;  M.re[1]=-s;  M.im[1]=0.f;
    M.re[2]=s;  M.im[2]=0.f;  M.re[3]=c;   M.im[3]=0.f;
    return M;
}
__device__ __forceinline__ C2x2 mk_u3(float t, float p, float l) {
    float c = cosf(0.5f*t), s = sinf(0.5f*t);
    C2x2 M;
    M.re[0]=c;              M.im[0]=0.f;
    M.re[1]=-cosf(l)*s;     M.im[1]=-sinf(l)*s;
    M.re[2]= cosf(p)*s;     M.im[2]= sinf(p)*s;
    M.re[3]= cosf(p+l)*c;   M.im[3]= sinf(p+l)*c;
    return M;
}

// ---------------------------------------------------------------------------
// Warp-level circuit sim primitives (validated R1)
// ---------------------------------------------------------------------------
__device__ __forceinline__ void apply_gate(const float* __restrict__ gp, int q, int lane,
                                           float& ar0, float& ai0, float& ar1, float& ai1) {
    float4 gA = *(const float4*)gp;
    float4 gB = *(const float4*)(gp + 4);
    if (q == 5) {
        float n0r = gA.x*ar0 - gA.y*ai0 + gA.z*ar1 - gA.w*ai1;
        float n0i = gA.x*ai0 + gA.y*ar0 + gA.z*ai1 + gA.w*ar1;
        float n1r = gB.x*ar0 - gB.y*ai0 + gB.z*ar1 - gB.w*ai1;
        float n1i = gB.x*ai0 + gB.y*ar0 + gB.z*ai1 + gB.w*ar1;
        ar0=n0r; ai0=n0i; ar1=n1r; ai1=n1i;
    } else {
        int sh = 4 - q;
        int lx = 1 << sh;
        int bit = (lane >> sh) & 1;
        float br0 = __shfl_xor_sync(0xffffffffu, ar0, lx);
        float bi0 = __shfl_xor_sync(0xffffffffu, ai0, lx);
        float br1 = __shfl_xor_sync(0xffffffffu, ar1, lx);
        float bi1 = __shfl_xor_sync(0xffffffffu, ai1, lx);
        float csr = bit ? gB.z : gA.x;
        float csi = bit ? gB.w : gA.y;
        float cor = bit ? gB.x : gA.z;
        float coi = bit ? gB.y : gA.w;
        float n0r = csr*ar0 - csi*ai0 + cor*br0 - coi*bi0;
        float n0i = csr*ai0 + csi*ar0 + cor*bi0 + coi*br0;
        float n1r = csr*ar1 - csi*ai1 + cor*br1 - coi*bi1;
        float n1i = csr*ai1 + csi*ar1 + cor*bi1 + coi*br1;
        ar0=n0r; ai0=n0i; ar1=n1r; ai1=n1i;
    }
}

__device__ __forceinline__ void apply_section(const float* __restrict__ sg, int base, int lane,
                                              float& ar0, float& ai0, float& ar1, float& ai1) {
    #pragma unroll
    for (int i = 0; i < 6; i++)
        apply_gate(sg + (base + i) * 8, i, lane, ar0, ai0, ar1, ai1);
}

__device__ __forceinline__ void apply_chain(int lane,
                                            float& ar0, float& ai0, float& ar1, float& ai1) {
    #pragma unroll
    for (int i = 0; i < 4; i++) {
        int lx = 1 << (3 - i);
        int cb = (lane >> (4 - i)) & 1;
        float br0 = __shfl_xor_sync(0xffffffffu, ar0, lx);
        float bi0 = __shfl_xor_sync(0xffffffffu, ai0, lx);
        float br1 = __shfl_xor_sync(0xffffffffu, ar1, lx);
        float bi1 = __shfl_xor_sync(0xffffffffu, ai1, lx);
        if (cb) { ar0=br0; ai0=bi0; ar1=br1; ai1=bi1; }
    }
    {
        int cb = lane & 1;
        float tr = ar0, ti = ai0;
        ar0 = cb ? ar1 : ar0;  ai0 = cb ? ai1 : ai0;
        ar1 = cb ? tr  : ar1;  ai1 = cb ? ti  : ai1;
    }
}

__device__ __forceinline__ float wredsum(float v) {
    #pragma unroll
    for (int o = 16; o > 0; o >>= 1) v += __shfl_xor_sync(0xffffffffu, v, o);
    return v;
}

// ---------------------------------------------------------------------------
// Precompute (validated 17 us config)
// ---------------------------------------------------------------------------
__global__ void precompute_kernel(const float* __restrict__ enc_w,
                                  const float* __restrict__ q_w,
                                  const float* __restrict__ k_w,
                                  const float* __restrict__ v_w,
                                  const float* __restrict__ mq,
                                  const float* __restrict__ mk,
                                  const float* __restrict__ mv,
                                  const float* __restrict__ qW,
                                  const float* __restrict__ kW,
                                  const float* __restrict__ raw_tau) {
    __shared__ __align__(16) float sg[576];
    int tid = threadIdx.x;

    if (tid < 72) {
        int g = tid;
        const float* w; const float* mw = nullptr;
        int sec, i; bool is_enc;
        if (g < 18) { w = enc_w; sec = g/6; i = g%6; is_enc = true; }
        else {
            int gg = g - 18; int xq = gg/18; sec = (gg%18)/6; i = gg%6; is_enc = false;
            w  = (xq==0) ? q_w : (xq==1) ? k_w : v_w;
            mw = (xq==0) ? mq  : (xq==1) ? mk  : mv;
        }
        C2x2 G;
        if (sec == 0)      G = cmul(mk_ry(w[i*3+1]), mk_rx(w[i*3+0]));
        else if (sec == 1) G = cmul(cmul(mk_ry(w[18+i*3+1]), mk_rx(w[18+i*3+0])),
                                    mk_ry(w[i*3+2]));
        else {
            if (is_enc) G = mk_ry(w[18+i*3+2]);
            else        G = cmul(mk_u3(mw[i*3+0], mw[i*3+1], mw[i*3+2]),
                                 mk_ry(w[18+i*3+2]));
        }
        float* o = &sg[g*8];
        o[0]=G.re[0]; o[1]=G.im[0]; o[2]=G.re[1]; o[3]=G.im[1];
        o[4]=G.re[2]; o[5]=G.im[2]; o[6]=G.re[3]; o[7]=G.im[3];
    }

    if (blockIdx.x == 0) {
        if (tid == 200) {
            float tau = log1pf(expf(raw_tau[0])) + 1e-9f;
            g_c2 = -1.4426950408889634f / tau;
        }
        for (int e = tid; e < 512; e += 256) {
            int br = e >> 8, j = (e >> 6) & 3, a = e & 63;
            const float* w = br ? kW : qW;
            float acc = 0.f;
            #pragma unroll
            for (int i = 0; i < 6; i++) {
                float sgn = ((a >> (5 - i)) & 1) ? -1.f : 1.f;
                acc += w[j*6 + i] * sgn;
            }
            g_WZ[e] = acc;
        }
    }
    __syncthreads();

    int lane = tid & 31, warp = tid >> 5;
    int c = blockIdx.x * 8 + warp;

    float ar0 = (2*lane     == c) ? 1.f : 0.f;
    float ar1 = (2*lane + 1 == c) ? 1.f : 0.f;
    float ai0 = 0.f, ai1 = 0.f;

    apply_section(sg, 0,  lane, ar0, ai0, ar1, ai1);
    apply_chain(lane, ar0, ai0, ar1, ai1);
    apply_section(sg, 6,  lane, ar0, ai0, ar1, ai1);
    apply_chain(lane, ar0, ai0, ar1, ai1);
    apply_section(sg, 12, lane, ar0, ai0, ar1, ai1);

    float cr0 = ar0, ci0 = ai0, cr1 = ar1, ci1 = ai1;

    #pragma unroll
    for (int br = 0; br < 3; br++) {
        ar0 = cr0; ai0 = ci0; ar1 = cr1; ai1 = ci1;
        int gb = 18 + br * 18;
        apply_section(sg, gb,      lane, ar0, ai0, ar1, ai1);
        apply_chain(lane, ar0, ai0, ar1, ai1);
        apply_section(sg, gb + 6,  lane, ar0, ai0, ar1, ai1);
        apply_chain(lane, ar0, ai0, ar1, ai1);
        apply_section(sg, gb + 12, lane, ar0, ai0, ar1, ai1);

        float* base = &g_M[(br * 64 + c) * 128];
        *(float2*)&base[2*lane]      = make_float2(ar0, ar1);
        *(float2*)&base[64 + 2*lane] = make_float2(ai0, ai1);
    }
}

// ---------------------------------------------------------------------------
// f32x2 helpers (phase1)
// ---------------------------------------------------------------------------
__device__ __forceinline__ u64 pk2(float x) {
    u64 r; asm("mov.b64 %0, {%1, %1};" : "=l"(r) : "f"(x)); return r;
}
__device__ __forceinline__ void fma2(u64& d, u64 a, u64 b) {
    asm("fma.rn.f32x2 %0, %1, %2, %0;" : "+l"(d) : "l"(a), "l"(b));
}
__device__ __forceinline__ float ex2f(float x) {
    float y; asm("ex2.approx.ftz.f32 %0, %1;" : "=f"(y) : "f"(x)); return y;
}

// ---------------------------------------------------------------------------
// Phase 1: Q/K epilogue via WZ-GEMM (R15 validated); V epilogue now also
// smem-based: probs -> sP, per-token LN by 64 threads, direct transposed
// fp16 store to g_vt (removes warp reductions AND the sVT staging copy).
// smem floats: sX 64*68 | sMC 8320 | sInv 64 | sWZ 512 | sLN 16 |
//              sP 64*65 | sO 256
// ---------------------------------------------------------------------------
#define SX_STRIDE 68
#define SP_STRIDE 65
#define P1_SMEM_FLOATS (64*SX_STRIDE + 8320 + 64 + 512 + 16 + 64*SP_STRIDE + 256)

__global__ __launch_bounds__(256) void phase1_kernel(
    const float* __restrict__ x, const float* __restrict__ inp_scale,
    const float* __restrict__ qB, const float* __restrict__ kB,
    const float* __restrict__ lng, const float* __restrict__ lnb) {

    extern __shared__ __align__(16) float sm[];
    float* sX   = sm;
    float* sM   = sX + 64*SX_STRIDE;
    float* sC   = sM;
    float* sInv = sM + 8320;
    float* sWZ  = sInv + 64;
    float* sLN  = sWZ + 512;
    float* sP   = sLN + 16;               // 64*65 fp32 probs [a][t]
    float* sO   = sP + 64*SP_STRIDE;      // 256

    int tid = threadIdx.x;
    int lane = tid & 31, warp = tid >> 5;
    int tok0 = blockIdx.x * 64;

    {
        int t = tid & 63, cg = tid >> 6;
        const float4* xg = (const float4*)(x + (size_t)(tok0 + t) * 64 + cg * 16);
        #pragma unroll
        for (int i = 0; i < 4; i++) {
            float4 v = xg[i];
            int c = cg * 16 + i * 4;
            float4 sv = *(const float4*)(inp_scale + c);
            sX[(c+0)*SX_STRIDE + t] = v.x * sv.x;
            sX[(c+1)*SX_STRIDE + t] = v.y * sv.y;
            sX[(c+2)*SX_STRIDE + t] = v.z * sv.z;
            sX[(c+3)*SX_STRIDE + t] = v.w * sv.w;
        }
    }
    if (tid < 16)  sLN[tid] = (tid < 4) ? qB[tid] : (tid < 8) ? kB[tid-4]
                             : (tid < 12) ? lng[tid-8] : lnb[tid-12];
    for (int e = tid; e < 512; e += 256) sWZ[e] = g_WZ[e];
    __syncthreads();

    #pragma unroll
    for (int it = 0; it < 8; it++) {
        int t = it * 8 + warp;
        float a0 = sX[lane*SX_STRIDE + t];
        float a1 = sX[(lane+32)*SX_STRIDE + t];
        float s = wredsum(a0*a0 + a1*a1);
        if (lane == 0) {
            float nr = sqrtf(s) + 1e-9f;
            sInv[t] = 1.f / (nr * nr);
        }
    }

    int rg = tid & 15, tg = tid >> 4;
    int r0 = rg * 8, t0 = tg * 4;

    for (int br = 0; br < 3; br++) {
        __syncthreads();
        {
            const float4* mg = (const float4*)&g_M[br * 64 * 128];
            float4* ms = (float4*)sM;
            #pragma unroll
            for (int i = 0; i < 8; i++) ms[i * 256 + tid] = mg[i * 256 + tid];
        }
        __syncthreads();

        u64 acc[4][4] = {};
        #pragma unroll 4
        for (int k = 0; k < 64; k++) {
            ulonglong2 mA = *(const ulonglong2*)&sM[k*128 + r0];
            ulonglong2 mB = *(const ulonglong2*)&sM[k*128 + r0 + 4];
            float4 xv = *(const float4*)&sX[k*SX_STRIDE + t0];
            u64 x0 = pk2(xv.x), x1 = pk2(xv.y), x2 = pk2(xv.z), x3 = pk2(xv.w);
            fma2(acc[0][0], mA.x, x0); fma2(acc[0][1], mA.x, x1);
            fma2(acc[0][2], mA.x, x2); fma2(acc[0][3], mA.x, x3);
            fma2(acc[1][0], mA.y, x0); fma2(acc[1][1], mA.y, x1);
            fma2(acc[1][2], mA.y, x2); fma2(acc[1][3], mA.y, x3);
            fma2(acc[2][0], mB.x, x0); fma2(acc[2][1], mB.x, x1);
            fma2(acc[2][2], mB.x, x2); fma2(acc[2][3], mB.x, x3);
            fma2(acc[3][0], mB.y, x0); fma2(acc[3][1], mB.y, x1);
            fma2(acc[3][2], mB.y, x2); fma2(acc[3][3], mB.y, x3);
        }
        __syncthreads();
        #pragma unroll
        for (int j = 0; j < 4; j++)
            #pragma unroll
            for (int i = 0; i < 4; i++)
                *(u64*)&sC[(t0+j)*130 + r0 + 2*i] = acc[i][j];
        __syncthreads();

        // probs -> sP[a][t]  (all branches)
        #pragma unroll
        for (int it = 0; it < 8; it++) {
            int t = it * 8 + warp;
            float inv = sInv[t];
            float2 re = *(float2*)&sC[t*130 + 2*lane];
            float2 im = *(float2*)&sC[t*130 + 64 + 2*lane];
            sP[(2*lane)  *SP_STRIDE + t] = (re.x*re.x + im.x*im.x) * inv;
            sP[(2*lane+1)*SP_STRIDE + t] = (re.y*re.y + im.y*im.y) * inv;
        }
        __syncthreads();

        if (br < 2) {
            // GEMM2: o[j][t] = bias_j + sum_a WZ[j][a] * P[a][t]
            {
                int j = tid >> 6, t = tid & 63;
                const float* wz = &sWZ[br*256 + j*64];
                float o = sLN[br*4 + j];
                #pragma unroll 8
                for (int a = 0; a < 64; a++)
                    o += wz[a] * sP[a*SP_STRIDE + t];
                sO[j*64 + t] = o;
            }
            __syncthreads();

            if (tid < 64) {
                int t = tid;
                float o0 = sO[t], o1 = sO[64+t], o2 = sO[128+t], o3 = sO[192+t];
                float m = 0.25f * (o0+o1+o2+o3);
                float d0=o0-m, d1=o1-m, d2=o2-m, d3=o3-m;
                float var = 0.25f * (d0*d0 + d1*d1 + d2*d2 + d3*d3);
                float rstd = rsqrtf(var + 1e-5f);
                float r0v = d0*rstd*sLN[8]  + sLN[12];
                float r1v = d1*rstd*sLN[9]  + sLN[13];
                float r2v = d2*rstd*sLN[10] + sLN[14];
                float r3v = d3*rstd*sLN[11] + sLN[15];
                float qq = r0v*r0v + r1v*r1v + r2v*r2v + r3v*r3v;
                int token = tok0 + t;
                if (br == 0) {
                    g_q[token] = make_float4(r0v, r1v, r2v, r3v);
                    g_qq[token] = qq;
                } else {
                    float c2l = g_c2;
                    float s2 = -2.f * c2l;
                    g_k[token] = make_float4(r0v*s2, r1v*s2, r2v*s2, r3v*s2);
                    g_kk[token] = c2l * qq;
                }
            }
        } else {
            // per-token mean / rstd (64 threads, streaming LDS)
            if (tid < 64) {
                int t = tid;
                float s1 = 0.f, s2 = 0.f;
                #pragma unroll 8
                for (int a = 0; a < 64; a++) {
                    float p = sP[a*SP_STRIDE + t];
                    s1 += p; s2 += p*p;
                }
                float m = s1 * (1.f/64.f);
                float var = s2 * (1.f/64.f) - m*m;
                sO[t]      = m;
                sO[64 + t] = rsqrtf(var + 1e-5f);
            }
            __syncthreads();

            // direct transposed fp16 store to g_vt
            {
                int bb = tok0 >> 11, s0 = tok0 & 2047;
                #pragma unroll
                for (int e = tid; e < 2048; e += 256) {
                    int dim = e >> 5, i = e & 31;
                    int t2 = 2*i;
                    float m0 = sO[t2],   rs0 = sO[64 + t2];
                    float m1 = sO[t2+1], rs1 = sO[64 + t2 + 1];
                    float v0 = (sP[dim*SP_STRIDE + t2]     - m0) * rs0;
                    float v1 = (sP[dim*SP_STRIDE + t2 + 1] - m1) * rs1;
                    __half2 hv = __floats2half2_rn(v0, v1);
                    *(__half2*)&g_vt[((size_t)bb*64 + dim)*SEQ + s0 + t2] = hv;
                }
            }
        }
    }
}

// ---------------------------------------------------------------------------
// Phase 2: FA2 + alpha pipelined one chunk ahead + 8 V buffers with
// stage-FOUR-ahead so __syncthreads fires only every FOURTH chunk.
// ---------------------------------------------------------------------------
__device__ __forceinline__ uint32_t smem_to_u32(const void* p) {
    uint32_t a;
    asm("{ .reg .u64 t; cvta.to.shared.u64 t, %1; cvt.u32.u64 %0, t; }"
        : "=r"(a) : "l"(p));
    return a;
}

#define LDSM_X4(r, a) \
    asm volatile("ldmatrix.sync.aligned.m8n8.x4.shared.b16 {%0,%1,%2,%3}, [%4];" \
                 : "=r"((r)[0]), "=r"((r)[1]), "=r"((r)[2]), "=r"((r)[3]) : "r"(a))

__device__ __forceinline__ void mma_f16(float* d, const uint32_t* a, const uint32_t* b) {
    asm volatile(
        "mma.sync.aligned.m16n8k16.row.col.f32.f16.f16.f32 "
        "{%0,%1,%2,%3}, {%4,%5,%6,%7}, {%8,%9}, {%0,%1,%2,%3};"
        : "+f"(d[0]), "+f"(d[1]), "+f"(d[2]), "+f"(d[3])
        : "r"(a[0]), "r"(a[1]), "r"(a[2]), "r"(a[3]), "r"(b[0]), "r"(b[1]));
}

__device__ __forceinline__ void alpha_chunk(
    int kb, int l3, const float4& q0, const float4& q1,
    float qs0, float qs1, uint32_t Af[4][4], float& d0, float& d1) {
    #pragma unroll
    for (int kf = 0; kf < 4; kf++) {
        int kidx = kb + kf * 16 + l3 * 2;
        #pragma unroll
        for (int cc = 0; cc < 2; cc++) {
            int ki = kidx + cc * 8;
            float4 ka = g_k[ki];
            float4 kb4 = g_k[ki + 1];
            float2 kk2 = *(const float2*)&g_kk[ki];
            float e00 = qs0 + kk2.x + ka.x*q0.x + ka.y*q0.y + ka.z*q0.z + ka.w*q0.w;
            float e01 = qs0 + kk2.y + kb4.x*q0.x + kb4.y*q0.y + kb4.z*q0.z + kb4.w*q0.w;
            float e10 = qs1 + kk2.x + ka.x*q1.x + ka.y*q1.y + ka.z*q1.z + ka.w*q1.w;
            float e11 = qs1 + kk2.y + kb4.x*q1.x + kb4.y*q1.y + kb4.z*q1.z + kb4.w*q1.w;
            float a00 = ex2f(fminf(e00, 0.f));
            float a01 = ex2f(fminf(e01, 0.f));
            float a10 = ex2f(fminf(e10, 0.f));
            float a11 = ex2f(fminf(e11, 0.f));
            d0 += a00 + a01;
            d1 += a10 + a11;
            __half2 h0 = __floats2half2_rn(a00, a01);
            __half2 h1 = __floats2half2_rn(a10, a11);
            Af[kf][cc*2 + 0] = *(uint32_t*)&h0;
            Af[kf][cc*2 + 1] = *(uint32_t*)&h1;
        }
    }
}

#define OFF_QV   0        // 2048
#define OFF_QQ   2048     // 512
#define OFF_B0   4096     // 8 buffers x 8192
#define P2_SMEM  (4096 + 8*8192)

__global__ __launch_bounds__(256, 2) void phase2_mma_kernel(float* __restrict__ out) {
    extern __shared__ __align__(1024) char smem[];
    uint32_t sbase = smem_to_u32(smem);
    int tid = threadIdx.x, lane = tid & 31, w = tid >> 5;
    int b = blockIdx.y;
    int qbase = b * SEQ + blockIdx.x * 128;

    float4* qv = (float4*)(smem + OFF_QV);
    float*  qq = (float*)(smem + OFF_QQ);

    if (tid < 128) { qv[tid] = g_q[qbase + tid]; qq[tid] = g_qq[qbase + tid]; }

    const __half* vt_base = g_vt + (size_t)b * 64 * SEQ;

    int vd0 = tid >> 3,         vo0 = tid & 7;
    int vd1 = (tid + 256) >> 3, vo1 = tid & 7;
    uint32_t voff0 = vd0 * 128 + ((vo0 ^ (vd0 & 7)) * 16);
    uint32_t voff1 = vd1 * 128 + ((vo1 ^ (vd1 & 7)) * 16);

    // prologue: fill buffers 0..3 (chunks 0..3); prefetch chunk 4
    #pragma unroll
    for (int c = 0; c < 4; c++) {
        uint4 a0 = *(const uint4*)(vt_base + (size_t)vd0 * SEQ + c*64 + vo0 * 8);
        uint4 a1 = *(const uint4*)(vt_base + (size_t)vd1 * SEQ + c*64 + vo1 * 8);
        *(uint4*)(smem + OFF_B0 + c*8192 + voff0) = a0;
        *(uint4*)(smem + OFF_B0 + c*8192 + voff1) = a1;
    }
    uint4 pv0 = *(const uint4*)(vt_base + (size_t)vd0 * SEQ + 256 + vo0 * 8);
    uint4 pv1 = *(const uint4*)(vt_base + (size_t)vd1 * SEQ + 256 + vo1 * 8);
    __syncthreads();

    int l3 = lane & 3, rloc = lane >> 2;
    int r0 = w * 16 + rloc, r1 = r0 + 8;
    float4 q0 = qv[r0], q1 = qv[r1];
    float c2 = g_c2;
    float qs0 = c2 * qq[r0], qs1 = c2 * qq[r1];

    float d0 = 0.f, d1 = 0.f;
    float acc[8][4] = {};

    int b_rloc = lane & 7;
    int b_cbo  = lane >> 3;

    uint32_t Af[4][4], Afn[4][4];
    alpha_chunk(b * SEQ, l3, q0, q1, qs0, qs1, Af, d0, d1);

    for (int kc = 0; kc < 32; kc++) {
        uint32_t bufR = OFF_B0 + (kc & 7) * 8192;

        // stage chunk kc+4 (prefetched), prefetch chunk kc+5
        if (kc < 28) {
            uint32_t bufW = OFF_B0 + ((kc + 4) & 7) * 8192;
            *(uint4*)(smem + bufW + voff0) = pv0;
            *(uint4*)(smem + bufW + voff1) = pv1;
            if (kc < 27) {
                int kn = (kc + 5) * 64;
                pv0 = *(const uint4*)(vt_base + (size_t)vd0 * SEQ + kn + vo0 * 8);
                pv1 = *(const uint4*)(vt_base + (size_t)vd1 * SEQ + kn + vo1 * 8);
            }
        }
        // alpha for next chunk (independent FFMA/MUFU stream)
        if (kc < 31)
            alpha_chunk(b * SEQ + (kc + 1) * 64, l3, q0, q1, qs0, qs1, Afn, d0, d1);

        // MMA stream for current chunk
        #pragma unroll
        for (int nt = 0; nt < 8; nt++) {
            uint32_t Bh[8];
            int brow = nt * 8 + b_rloc;
            #pragma unroll
            for (int ks2 = 0; ks2 < 2; ks2++) {
                int cb = ks2 * 4 + b_cbo;
                uint32_t addr = sbase + bufR + brow * 128 + ((cb ^ (brow & 7)) * 16);
                LDSM_X4(&Bh[ks2*4], addr);
            }
            #pragma unroll
            for (int kf = 0; kf < 4; kf++)
                mma_f16(acc[nt], Af[kf], &Bh[kf*2]);
        }

        #pragma unroll
        for (int kf = 0; kf < 4; kf++)
            #pragma unroll
            for (int j = 0; j < 4; j++)
                Af[kf][j] = Afn[kf][j];

        if ((kc & 3) == 3) __syncthreads();   // barrier every FOURTH chunk
    }

    d0 += __shfl_xor_sync(0xffffffffu, d0, 1);
    d0 += __shfl_xor_sync(0xffffffffu, d0, 2);
    d1 += __shfl_xor_sync(0xffffffffu, d1, 1);
    d1 += __shfl_xor_sync(0xffffffffu, d1, 2);
    float rdT = 1.f / (d0 + 1e-9f);
    float rdB = 1.f / (d1 + 1e-9f);

    int cl = l3 * 2;
    #pragma unroll
    for (int nt = 0; nt < 8; nt++) {
        *(float2*)&out[(size_t)(qbase + r0) * 64 + nt*8 + cl] =
            make_float2(acc[nt][0] * rdT, acc[nt][1] * rdT);
        *(float2*)&out[(size_t)(qbase + r1) * 64 + nt*8 + cl] =
            make_float2(acc[nt][2] * rdB, acc[nt][3] * rdB);
    }
}

// ---------------------------------------------------------------------------
// Launch
// ---------------------------------------------------------------------------
extern "C" void kernel_launch(void* const* d_in, const int* in_sizes, int n_in,
                              void* d_out, int out_size) {
    const float* x         = (const float*)d_in[0];
    const float* inp_scale = (const float*)d_in[1];
    const float* enc_w     = (const float*)d_in[2];
    const float* q_w       = (const float*)d_in[3];
    const float* k_w       = (const float*)d_in[4];
    const float* v_w       = (const float*)d_in[5];
    const float* mq        = (const float*)d_in[6];
    const float* mk        = (const float*)d_in[7];
    const float* mv        = (const float*)d_in[8];
    const float* qW        = (const float*)d_in[9];
    const float* qB        = (const float*)d_in[10];
    const float* kW        = (const float*)d_in[11];
    const float* kB        = (const float*)d_in[12];
    const float* lng       = (const float*)d_in[13];
    const float* lnb       = (const float*)d_in[14];
    const float* raw_tau   = (const float*)d_in[15];

    static int attr_set = 0;
    const int P1_SMEM = P1_SMEM_FLOATS * 4;
    if (!attr_set) {
        cudaFuncSetAttribute(phase1_kernel,
                             cudaFuncAttributeMaxDynamicSharedMemorySize, P1_SMEM);
        cudaFuncSetAttribute(phase2_mma_kernel,
                             cudaFuncAttributeMaxDynamicSharedMemorySize, P2_SMEM);
        attr_set = 1;
    }

    precompute_kernel<<<8, 256>>>(enc_w, q_w, k_w, v_w, mq, mk, mv, qW, kW, raw_tau);
    phase1_kernel<<<NTOK / 64, 256, P1_SMEM>>>(x, inp_scale, qB, kB, lng, lnb);
    phase2_mma_kernel<<<dim3(SEQ / 128, NBATCH), 256, P2_SMEM>>>((float*)d_out);
}